// round 10
// baseline (speedup 1.0000x reference)
#include <cuda_runtime.h>
#include <cstdint>

#define NUM_E   1024
#define DIM     128
#define HW      4096
#define NBLOCKS 512           // 65536 rows / 128 per CTA

// Output layout (flattened tuple, float32)
#define OFF_LOSS   8388608
#define OFF_IDX    8388609
#define OFF_COMMIT 8454145
#define OFF_CODE   8454146

#define MARGIN 1.2e-4f

__device__ float    d_enorm[NUM_E];
__device__ float    d_blockS[NBLOCKS];
__device__ __align__(16) uint32_t d_bfrag[16 * 64 * 32 * 4]; // [kg][nblk][lane][slot]
__device__ unsigned d_ctr = 0;

// SMEM (byte offsets) — total under 114KB for 2 CTAs/SM
#define SM_AHI  0          // A-hi frag layout, 64KB
#define SM_B    65536      // B staging: 2 x 16KB quarter-tile buffers
#define SM_E2   98304      // 1024 f32 (raw ||e||^2, refine)
#define SM_E2C  102400     // 1024 f32 (1 + ||e||^2, shortlist)
#define SM_Z2   106496     // 128 f32
#define SM_IDX  107008     // 128 i32
#define SM_WSUM 107520     // 8 f32
#define SM_FLAG 107552
#define SMEM_BYTES 107584
// cand[128][16] u64 (16KB) aliases SM_B after the mainloop

static __device__ __forceinline__ uint32_t smem_u32(const void* p) {
    uint32_t a;
    asm("{ .reg .u64 t; cvta.to.shared.u64 t, %1; cvt.u32.u64 %0, t; }"
        : "=r"(a) : "l"(p));
    return a;
}
static __device__ __forceinline__ uint32_t cvt_tf32(float x) {
    uint32_t b;
    asm("cvt.rna.tf32.f32 %0, %1;" : "=r"(b) : "f"(x));
    return b;
}
static __device__ __forceinline__ void mma8(float c[4], const uint32_t a[4],
                                            uint32_t b0, uint32_t b1) {
    asm("mma.sync.aligned.m16n8k8.row.col.f32.tf32.tf32.f32 "
        "{%0,%1,%2,%3}, {%4,%5,%6,%7}, {%8,%9}, {%0,%1,%2,%3};"
        : "+f"(c[0]), "+f"(c[1]), "+f"(c[2]), "+f"(c[3])
        : "r"(a[0]), "r"(a[1]), "r"(a[2]), "r"(a[3]), "r"(b0), "r"(b1));
}
static __device__ __forceinline__ void cp16(uint32_t dst, const void* src) {
    asm volatile("cp.async.cg.shared.global [%0], [%1], 16;"
                 :: "r"(dst), "l"(src) : "memory");
}
static __device__ __forceinline__ void cp_commit() {
    asm volatile("cp.async.commit_group;" ::: "memory");
}
static __device__ __forceinline__ void cp_wait1() {
    asm volatile("cp.async.wait_group 1;" ::: "memory");
}
// element (m 0..127, k 0..127) -> byte offset in A frag layout
static __device__ __forceinline__ int afrag_off(int m, int k) {
    int lane = ((m & 7) << 2) | (k & 3);
    int slot = ((m >> 3) & 1) | (((k >> 2) & 1) << 1);
    return ((((k >> 3) << 3) + (m >> 4)) << 9) + (lane << 4) + (slot << 2);
}

// ---------------------------------------------------------------------------
// Prep: ||e||^2 + tf32-hi codebook written directly in B-fragment order.
// ---------------------------------------------------------------------------
__global__ void prep_kernel(const float* __restrict__ emb) {
    int k    = blockIdx.x * 8 + (threadIdx.x >> 5);   // code id
    int lane = threadIdx.x & 31;
    const float4* row = (const float4*)(emb + (size_t)k * DIM);
    float4 v = row[lane];
    float s = __fadd_rn(__fadd_rn(__fmul_rn(v.x, v.x), __fmul_rn(v.y, v.y)),
                        __fadd_rn(__fmul_rn(v.z, v.z), __fmul_rn(v.w, v.w)));
    #pragma unroll
    for (int o = 16; o; o >>= 1) s = __fadd_rn(s, __shfl_xor_sync(0xffffffffu, s, o));
    if (lane == 0) d_enorm[k] = s;

    int nblk = k >> 4, nn = k & 15;
    float xv[4] = {v.x, v.y, v.z, v.w};
    #pragma unroll
    for (int e = 0; e < 4; e++) {
        int kk = lane * 4 + e;
        uint32_t hb = cvt_tf32(xv[e]);
        int kg   = kk >> 3;
        int fl   = ((nn & 7) << 2) | (kk & 3);
        int slot = ((kk >> 2) & 1) | (((nn >> 3) & 1) << 1);
        d_bfrag[(((kg << 6) + nblk) << 7) + (fl << 2) + slot] = hb;
    }
}

// ---------------------------------------------------------------------------
// Main: 512 CTAs x 256 threads, 2 CTAs/SM. warp_m = wid>>1, warp_n = wid&1.
// B streamed gmem -> SMEM by cp.async in 16KB quarter-j-tiles (4 kg each),
// double-buffered. 32 stages total (8 j-tiles x 4 quarters).
// ---------------------------------------------------------------------------
__global__ __launch_bounds__(256, 2)
void vq_main_kernel(const float* __restrict__ z,
                    const float* __restrict__ emb,
                    float* __restrict__ out) {
    extern __shared__ char smem[];
    const uint32_t sb = smem_u32(smem);
    float* e2sm  = (float*)(smem + SM_E2);
    float* e2c   = (float*)(smem + SM_E2C);
    float* z2sm  = (float*)(smem + SM_Z2);
    int*   idxsm = (int*)(smem + SM_IDX);
    float* wsum  = (float*)(smem + SM_WSUM);

    const int t    = threadIdx.x;
    const int wid  = t >> 5;
    const int lane = t & 31;
    const int warp_m = wid >> 1;              // 0..3
    const int warp_n = wid & 1;               // 0..1
    const int blk = blockIdx.x;
    const int n0  = blk * 128;
    const int b   = n0 >> 12;
    const int hw0 = n0 & 4095;
    const float* zbase = z + (size_t)b * (DIM * HW) + hw0;
    const char*  bgb   = (const char*)d_bfrag;

    // issue cp.async for pipeline stages s=0 and s=1 immediately
    #pragma unroll
    for (int s = 0; s < 2; s++) {
        uint32_t dst = sb + SM_B + (s & 1) * 16384 + t * 16;
        #pragma unroll
        for (int o = 0; o < 4; o++) {
            int kg_g = (s & 3) * 4 + o;
            const char* src = bgb + (((kg_g << 6) + ((s >> 2) << 3) + (t >> 5)) << 9)
                            + (lane & 31) * 16;
            cp16(dst + o * 4096, src);
        }
        cp_commit();
    }

    // e2 / e2c tables
    #pragma unroll
    for (int i = 0; i < 4; i++) {
        float e = d_enorm[i * 256 + t];
        e2sm[i * 256 + t] = e;
        e2c[i * 256 + t]  = 1.0f + e;
    }

    // ---- prologue: A-hi frags + strictly sequential z2 (z from gmem) ----
    if (t < 128) {
        float z2 = 0.f;
        #pragma unroll 8
        for (int d = 0; d < 128; d++) {
            float v = __ldg(zbase + (size_t)d * HW + t);
            z2 = __fadd_rn(z2, __fmul_rn(v, v));
            *(uint32_t*)(smem + SM_AHI + afrag_off(t, d)) = cvt_tf32(v);
        }
        z2sm[t] = z2;
    }

    unsigned long long best0[4], best1[4];
    #pragma unroll
    for (int i = 0; i < 4; i++) { best0[i] = ~0ull; best1[i] = ~0ull; }

    float acc[2][8][4];

    // ---- mainloop: 32 stages (8 j x 4 quarters of 4 kg) ----
    #pragma unroll 1
    for (int s = 0; s < 32; s++) {
        const int j   = s >> 2;
        const int qtr = s & 3;

        if (qtr == 0) {
            #pragma unroll
            for (int mf = 0; mf < 2; mf++)
                #pragma unroll
                for (int nf = 0; nf < 8; nf++)
                    #pragma unroll
                    for (int q = 0; q < 4; q++) acc[mf][nf][q] = 0.f;
        }

        cp_wait1();                     // stage s data resident
        __syncthreads();                // visible to all; prior reads done

        // mma over the 4 kg of this quarter-tile
        #pragma unroll
        for (int kgl = 0; kgl < 4; kgl++) {
            const int kg = qtr * 4 + kgl;
            uint4 af[2], bf[4];
            #pragma unroll
            for (int mf = 0; mf < 2; mf++)
                af[mf] = *(const uint4*)(smem + SM_AHI
                       + (((kg << 3) + (warp_m << 1) + mf) << 9) + (lane << 4));
            #pragma unroll
            for (int i = 0; i < 4; i++)
                bf[i] = *(const uint4*)(smem + SM_B + (s & 1) * 16384
                      + kgl * 4096 + ((warp_n << 2) + i) * 512 + lane * 16);
            #pragma unroll
            for (int mf = 0; mf < 2; mf++) {
                const uint32_t* av = (const uint32_t*)&af[mf];
                #pragma unroll
                for (int i = 0; i < 4; i++) {
                    mma8(acc[mf][i * 2 + 0], av, bf[i].x, bf[i].y);
                    mma8(acc[mf][i * 2 + 1], av, bf[i].z, bf[i].w);
                }
            }
        }
        __syncthreads();                // all warps done reading buffer s&1

        if (s + 2 < 32) {               // prefetch stage s+2 into buffer s&1
            const int s2 = s + 2;
            uint32_t dst = sb + SM_B + (s & 1) * 16384 + t * 16;
            #pragma unroll
            for (int o = 0; o < 4; o++) {
                int kg_g = (s2 & 3) * 4 + o;
                const char* src = bgb + (((kg_g << 6) + ((s2 >> 2) << 3) + (t >> 5)) << 9)
                                + (lane & 31) * 16;
                cp16(dst + o * 4096, src);
            }
            cp_commit();
        } else {
            cp_commit();                // keep wait_group(1) accounting uniform
        }

        if (qtr == 3) {
            // shortlist scoring: s = fl((1+e2) - 2*dot); z2 dropped (row-const)
            float e2v[8][2];
            int   ncb[8];
            #pragma unroll
            for (int nf = 0; nf < 8; nf++) {
                ncb[nf] = j * 128 + warp_n * 64 + nf * 8 + ((lane & 3) << 1);
                e2v[nf][0] = e2c[ncb[nf]];
                e2v[nf][1] = e2c[ncb[nf] + 1];
            }
            #pragma unroll
            for (int mf = 0; mf < 2; mf++)
                #pragma unroll
                for (int nf = 0; nf < 8; nf++)
                    #pragma unroll
                    for (int h = 0; h < 2; h++)
                        #pragma unroll
                        for (int q = 0; q < 2; q++) {
                            float sv = __fmaf_rn(-2.0f, acc[mf][nf][h * 2 + q],
                                                 e2v[nf][q]);
                            unsigned long long u =
                                ((unsigned long long)__float_as_uint(sv) << 32)
                                | (unsigned)(ncb[nf] + q);
                            int sl = mf * 2 + h;
                            if (u < best0[sl]) { best1[sl] = best0[sl]; best0[sl] = u; }
                            else if (u < best1[sl]) { best1[sl] = u; }
                        }
        }
    }

    // ---- dump candidates: cand[m][16] (aliases B buffers) ----
    __syncthreads();
    unsigned long long* cand = (unsigned long long*)(smem + SM_B);
    {
        int ci = warp_n * 4 + (lane & 3);
        #pragma unroll
        for (int mf = 0; mf < 2; mf++)
            #pragma unroll
            for (int h = 0; h < 2; h++) {
                int m = warp_m * 32 + mf * 16 + h * 8 + (lane >> 2);
                cand[m * 16 + ci * 2 + 0] = best0[mf * 2 + h];
                cand[m * 16 + ci * 2 + 1] = best1[mf * 2 + h];
            }
    }
    __syncthreads();

    // ---- per-row: merge, margin-select, EXACT refine (z from gmem;
    //      accumulation order bit-identical to prior rounds) ----
    if (t < 128) {
        unsigned long long m0 = ~0ull;
        #pragma unroll
        for (int ci = 0; ci < 16; ci++) {
            unsigned long long u = cand[t * 16 + ci];
            if (u < m0) m0 = u;
        }
        float thr = __uint_as_float((uint32_t)(m0 >> 32)) + MARGIN;
        int cl[6]; int nc = 0;
        #pragma unroll
        for (int ci = 0; ci < 16; ci++) {
            unsigned long long u = cand[t * 16 + ci];
            float sv = __uint_as_float((uint32_t)(u >> 32));
            if (sv <= thr && nc < 6) cl[nc++] = (int)(u & 0xffffffffu);
        }
        float a[6][4];
        #pragma unroll
        for (int i = 0; i < 6; i++)
            #pragma unroll
            for (int p = 0; p < 4; p++) a[i][p] = 0.f;
        #pragma unroll 4
        for (int q = 0; q < 32; q++) {
            int d0 = q * 4;
            float zv0 = __ldg(zbase + (size_t)(d0 + 0) * HW + t);
            float zv1 = __ldg(zbase + (size_t)(d0 + 1) * HW + t);
            float zv2 = __ldg(zbase + (size_t)(d0 + 2) * HW + t);
            float zv3 = __ldg(zbase + (size_t)(d0 + 3) * HW + t);
            #pragma unroll
            for (int i = 0; i < 6; i++) {
                if (i < nc) {
                    float4 e4 = ((const float4*)(emb + (size_t)cl[i] * DIM))[q];
                    a[i][0] = fmaf(zv0, e4.x, a[i][0]);
                    a[i][1] = fmaf(zv1, e4.y, a[i][1]);
                    a[i][2] = fmaf(zv2, e4.z, a[i][2]);
                    a[i][3] = fmaf(zv3, e4.w, a[i][3]);
                }
            }
        }
        float z2 = z2sm[t];
        unsigned long long bestu = ~0ull;
        for (int i = 0; i < nc; i++) {
            float dot = __fadd_rn(__fadd_rn(a[i][0], a[i][1]),
                                  __fadd_rn(a[i][2], a[i][3]));
            float s = __fadd_rn(__fadd_rn(z2, e2sm[cl[i]]), __fmul_rn(-2.0f, dot));
            unsigned long long u =
                ((unsigned long long)__float_as_uint(s) << 32) | (unsigned)cl[i];
            if (u < bestu) bestu = u;
        }
        int idx = (int)(bestu & 0xffffffffu);
        idxsm[t] = idx;
        out[OFF_IDX + n0 + t] = (float)idx;
    }
    __syncthreads();

    // ---- epilogue: z_q gather+write, loss partial (z re-read coalesced) ----
    float sloc = 0.f;
    #pragma unroll 4
    for (int r = 0; r < 64; r++) {
        int linear = t + (r << 8);
        int d = linear >> 7;
        int n = linear & 127;
        float v  = emb[(size_t)idxsm[n] * DIM + d];
        float zv = __ldg(zbase + (size_t)d * HW + n);
        float diff = v - zv;
        sloc = fmaf(diff, diff, sloc);
        out[(size_t)b * (DIM * HW) + (size_t)d * HW + hw0 + n] = v;
    }
    #pragma unroll
    for (int o = 16; o; o >>= 1) sloc += __shfl_xor_sync(0xffffffffu, sloc, o);
    if (lane == 0) wsum[wid] = sloc;
    __syncthreads();
    if (t == 0) {
        float s = 0.f;
        #pragma unroll
        for (int i = 0; i < 8; i++) s += wsum[i];
        d_blockS[blk] = s;
        __threadfence();
        unsigned v = atomicAdd(&d_ctr, 1u);
        *(unsigned*)(smem + SM_FLAG) = (v == (unsigned)(gridDim.x - 1));
    }
    __syncthreads();

    // ---- last block: deterministic finalize ----
    if (*(unsigned*)(smem + SM_FLAG)) {
        float* scratch = (float*)(smem + SM_B);
        scratch[t] = d_blockS[t] + d_blockS[t + 256];
        __syncthreads();
        for (int s = 128; s > 0; s >>= 1) {
            if (t < s) scratch[t] += scratch[t + s];
            __syncthreads();
        }
        if (t == 0) {
            float S = scratch[0];
            out[OFF_LOSS]   = 1.25f * S;
            out[OFF_COMMIT] = 0.25f * S;
            out[OFF_CODE]   = S;
            d_ctr = 0;                          // reset for next graph replay
        }
    }
}

// ---------------------------------------------------------------------------
extern "C" void kernel_launch(void* const* d_in, const int* in_sizes, int n_in,
                              void* d_out, int out_size) {
    const float* z   = (const float*)d_in[0];   // (16, 128, 64, 64)
    const float* emb = (const float*)d_in[1];   // (1024, 128)
    float* out = (float*)d_out;

    cudaFuncSetAttribute(vq_main_kernel,
                         cudaFuncAttributeMaxDynamicSharedMemorySize, SMEM_BYTES);

    prep_kernel<<<128, 256>>>(emb);
    vq_main_kernel<<<NBLOCKS, 256, SMEM_BYTES>>>(z, emb, out);
}

// round 11
// speedup vs baseline: 1.2126x; 1.2126x over previous
#include <cuda_runtime.h>
#include <cstdint>

#define NUM_E   1024
#define DIM     128
#define HW      4096
#define NBLOCKS 512           // 65536 rows / 128 per CTA

// Output layout (flattened tuple, float32)
#define OFF_LOSS   8388608
#define OFF_IDX    8388609
#define OFF_COMMIT 8454145
#define OFF_CODE   8454146

#define MARGIN 8e-4f

__device__ float    d_enorm[NUM_E];
__device__ float    d_blockS[NBLOCKS];
// bf16 codebook in m16n8k16 B-fragment order, as 32-bit (bf16x2) words:
// [j 0..7][kg16 0..7][nb 0..7][lane 0..31][slot 0..3]
__device__ __align__(16) uint32_t d_bfrag16[65536];
__device__ unsigned d_ctr = 0;

// SMEM (byte offsets) — 107584 total, 2 CTAs/SM
#define SM_A    0          // A bf16 frag layout, 32KB
#define SM_B    32768      // B staging: 2 x 32KB j-tile buffers
#define SM_E2   98304      // 1024 f32 (raw ||e||^2, refine)
#define SM_E2C  102400     // 1024 f32 (1 + ||e||^2, shortlist)
#define SM_Z2   106496     // 128 f32
#define SM_IDX  107008     // 128 i32
#define SM_WSUM 107520     // 8 f32
#define SM_FLAG 107552
#define SMEM_BYTES 107584
// cand[128][24] u64 (24KB) aliases SM_B after the mainloop

static __device__ __forceinline__ uint32_t smem_u32(const void* p) {
    uint32_t a;
    asm("{ .reg .u64 t; cvta.to.shared.u64 t, %1; cvt.u32.u64 %0, t; }"
        : "=r"(a) : "l"(p));
    return a;
}
// pack two f32 -> bf16x2 (lo = first arg)
static __device__ __forceinline__ uint32_t pack_bf16x2(float lo, float hi) {
    uint32_t r;
    asm("cvt.rn.bf16x2.f32 %0, %1, %2;" : "=r"(r) : "f"(hi), "f"(lo));
    return r;
}
static __device__ __forceinline__ void mma16(float c[4], const uint32_t a[4],
                                             uint32_t b0, uint32_t b1) {
    asm("mma.sync.aligned.m16n8k16.row.col.f32.bf16.bf16.f32 "
        "{%0,%1,%2,%3}, {%4,%5,%6,%7}, {%8,%9}, {%0,%1,%2,%3};"
        : "+f"(c[0]), "+f"(c[1]), "+f"(c[2]), "+f"(c[3])
        : "r"(a[0]), "r"(a[1]), "r"(a[2]), "r"(a[3]), "r"(b0), "r"(b1));
}
static __device__ __forceinline__ void cp16(uint32_t dst, const void* src) {
    asm volatile("cp.async.cg.shared.global [%0], [%1], 16;"
                 :: "r"(dst), "l"(src) : "memory");
}
static __device__ __forceinline__ void cp_commit() {
    asm volatile("cp.async.commit_group;" ::: "memory");
}
static __device__ __forceinline__ void cp_wait1() {
    asm volatile("cp.async.wait_group 1;" ::: "memory");
}

// ---------------------------------------------------------------------------
// Prep: ||e||^2 + bf16 codebook in m16n8k16 B-fragment order.
// 128 blocks x 256 threads, one warp per code.
// ---------------------------------------------------------------------------
__global__ void prep_kernel(const float* __restrict__ emb) {
    int k    = blockIdx.x * 8 + (threadIdx.x >> 5);   // code id
    int lane = threadIdx.x & 31;
    const float4* row = (const float4*)(emb + (size_t)k * DIM);
    float4 v = row[lane];
    float s = __fadd_rn(__fadd_rn(__fmul_rn(v.x, v.x), __fmul_rn(v.y, v.y)),
                        __fadd_rn(__fmul_rn(v.z, v.z), __fmul_rn(v.w, v.w)));
    #pragma unroll
    for (int o = 16; o; o >>= 1) s = __fadd_rn(s, __shfl_xor_sync(0xffffffffu, s, o));
    if (lane == 0) d_enorm[k] = s;

    int j = k >> 7, loc = k & 127;
    int nb = loc >> 4, nn = loc & 15;
    int sub = nn >> 3, g = nn & 7;
    float vv[4] = {v.x, v.y, v.z, v.w};
    #pragma unroll
    for (int w = 0; w < 2; w++) {
        int d    = lane * 4 + w * 2;
        int kg   = d >> 4;
        int half = (d >> 3) & 1;
        int tig  = (d & 7) >> 1;
        int lane_f = g * 4 + tig;
        int slot = sub * 2 + half;
        uint32_t word = pack_bf16x2(vv[w * 2], vv[w * 2 + 1]);
        d_bfrag16[((((j * 8 + kg) * 8 + nb) * 32 + lane_f) * 4) + slot] = word;
    }
}

// ---------------------------------------------------------------------------
// Main: 512 CTAs x 256 threads, 2 CTAs/SM. warp_m = wid>>1, warp_n = wid&1.
// bf16 m16n8k16. B streamed gmem->SMEM in full 32KB j-tiles, double-buffered.
// 8 stages (one per j-tile), 16 barriers total.
// ---------------------------------------------------------------------------
__global__ __launch_bounds__(256, 2)
void vq_main_kernel(const float* __restrict__ z,
                    const float* __restrict__ emb,
                    float* __restrict__ out) {
    extern __shared__ char smem[];
    const uint32_t sb = smem_u32(smem);
    float* e2sm  = (float*)(smem + SM_E2);
    float* e2c   = (float*)(smem + SM_E2C);
    float* z2sm  = (float*)(smem + SM_Z2);
    int*   idxsm = (int*)(smem + SM_IDX);
    float* wsum  = (float*)(smem + SM_WSUM);

    const int t    = threadIdx.x;
    const int wid  = t >> 5;
    const int lane = t & 31;
    const int warp_m = wid >> 1;              // 0..3
    const int warp_n = wid & 1;               // 0..1
    const int blk = blockIdx.x;
    const int n0  = blk * 128;
    const int b   = n0 >> 12;
    const int hw0 = n0 & 4095;
    const float* zbase = z + (size_t)b * (DIM * HW) + hw0;
    const char*  bgb   = (const char*)d_bfrag16;

    // prefetch stages j=0,1 (full 32KB each; 8 cp16 per thread)
    #pragma unroll
    for (int s = 0; s < 2; s++) {
        uint32_t dst = sb + SM_B + s * 32768 + t * 16;
        const char* src = bgb + s * 32768 + t * 16;
        #pragma unroll
        for (int o = 0; o < 8; o++)
            cp16(dst + o * 4096, src + o * 4096);
        cp_commit();
    }

    // e2 / e2c tables
    #pragma unroll
    for (int i = 0; i < 4; i++) {
        float e = d_enorm[i * 256 + t];
        e2sm[i * 256 + t] = e;
        e2c[i * 256 + t]  = 1.0f + e;
    }

    // ---- prologue: A bf16 frags + strictly sequential z2 (z from gmem) ----
    if (t < 128) {
        const int mt = t >> 4, mm = t & 15;
        const int hm = mm >> 3, g = mm & 7;
        float z2 = 0.f;
        #pragma unroll 4
        for (int dp = 0; dp < 64; dp++) {
            int d = dp * 2;
            float v0 = __ldg(zbase + (size_t)d * HW + t);
            float v1 = __ldg(zbase + (size_t)(d + 1) * HW + t);
            z2 = __fadd_rn(__fadd_rn(z2, __fmul_rn(v0, v0)), __fmul_rn(v1, v1));
            int kg = d >> 4, half = (d >> 3) & 1, tig = (d & 7) >> 1;
            int reg = hm + 2 * half;
            int lane_f = g * 4 + tig;
            *(uint32_t*)(smem + SM_A
                + ((((kg * 8 + mt) * 32 + lane_f) * 4 + reg) << 2))
                = pack_bf16x2(v0, v1);
        }
        z2sm[t] = z2;
    }

    unsigned long long best0[4], best1[4], best2[4];
    #pragma unroll
    for (int i = 0; i < 4; i++) { best0[i] = ~0ull; best1[i] = ~0ull; best2[i] = ~0ull; }

    // ---- mainloop: 8 stages (one j-tile each) ----
    #pragma unroll 1
    for (int j = 0; j < 8; j++) {
        float acc[2][8][4];
        #pragma unroll
        for (int mf = 0; mf < 2; mf++)
            #pragma unroll
            for (int nf = 0; nf < 8; nf++)
                #pragma unroll
                for (int q = 0; q < 4; q++) acc[mf][nf][q] = 0.f;

        cp_wait1();                     // stage j data resident
        __syncthreads();                // visible to all; prior reads done

        const int bbuf = SM_B + (j & 1) * 32768;
        #pragma unroll
        for (int kg = 0; kg < 8; kg++) {
            uint4 af[2], bf[4];
            #pragma unroll
            for (int mf = 0; mf < 2; mf++)
                af[mf] = *(const uint4*)(smem + SM_A + kg * 4096
                       + (warp_m * 2 + mf) * 512 + lane * 16);
            #pragma unroll
            for (int i = 0; i < 4; i++)
                bf[i] = *(const uint4*)(smem + bbuf + kg * 4096
                      + (warp_n * 4 + i) * 512 + lane * 16);
            #pragma unroll
            for (int mf = 0; mf < 2; mf++) {
                const uint32_t* av = (const uint32_t*)&af[mf];
                #pragma unroll
                for (int i = 0; i < 4; i++) {
                    mma16(acc[mf][i * 2 + 0], av, bf[i].x, bf[i].y);
                    mma16(acc[mf][i * 2 + 1], av, bf[i].z, bf[i].w);
                }
            }
        }
        __syncthreads();                // all warps done reading buffer j&1

        if (j + 2 < 8) {                // prefetch stage j+2 into buffer j&1
            uint32_t dst = sb + SM_B + (j & 1) * 32768 + t * 16;
            const char* src = bgb + (j + 2) * 32768 + t * 16;
            #pragma unroll
            for (int o = 0; o < 8; o++)
                cp16(dst + o * 4096, src + o * 4096);
            cp_commit();
        } else {
            cp_commit();                // keep wait_group(1) accounting uniform
        }

        // shortlist scoring: s = fl((1+e2) - 2*dot); top-3 per (thread,slot)
        float e2v[8][2];
        int   ncb[8];
        #pragma unroll
        for (int nf = 0; nf < 8; nf++) {
            ncb[nf] = j * 128 + warp_n * 64 + nf * 8 + ((lane & 3) << 1);
            e2v[nf][0] = e2c[ncb[nf]];
            e2v[nf][1] = e2c[ncb[nf] + 1];
        }
        #pragma unroll
        for (int mf = 0; mf < 2; mf++)
            #pragma unroll
            for (int nf = 0; nf < 8; nf++)
                #pragma unroll
                for (int h = 0; h < 2; h++)
                    #pragma unroll
                    for (int q = 0; q < 2; q++) {
                        float sv = __fmaf_rn(-2.0f, acc[mf][nf][h * 2 + q],
                                             e2v[nf][q]);
                        unsigned long long u =
                            ((unsigned long long)__float_as_uint(sv) << 32)
                            | (unsigned)(ncb[nf] + q);
                        int sl = mf * 2 + h;
                        if (u < best0[sl]) {
                            best2[sl] = best1[sl]; best1[sl] = best0[sl]; best0[sl] = u;
                        } else if (u < best1[sl]) {
                            best2[sl] = best1[sl]; best1[sl] = u;
                        } else if (u < best2[sl]) {
                            best2[sl] = u;
                        }
                    }
    }

    // ---- dump candidates: cand[m][24] (aliases B buffers) ----
    __syncthreads();
    unsigned long long* cand = (unsigned long long*)(smem + SM_B);
    {
        int ci = warp_n * 4 + (lane & 3);          // 0..7
        #pragma unroll
        for (int mf = 0; mf < 2; mf++)
            #pragma unroll
            for (int h = 0; h < 2; h++) {
                int m = warp_m * 32 + mf * 16 + h * 8 + (lane >> 2);
                int sl = mf * 2 + h;
                cand[m * 24 + ci * 3 + 0] = best0[sl];
                cand[m * 24 + ci * 3 + 1] = best1[sl];
                cand[m * 24 + ci * 3 + 2] = best2[sl];
            }
    }
    __syncthreads();

    // ---- per-row: merge, margin-select, EXACT refine (bit-identical to R10) --
    if (t < 128) {
        unsigned long long m0 = ~0ull;
        #pragma unroll
        for (int ci = 0; ci < 24; ci++) {
            unsigned long long u = cand[t * 24 + ci];
            if (u < m0) m0 = u;
        }
        float thr = __uint_as_float((uint32_t)(m0 >> 32)) + MARGIN;
        int cl[8]; int nc = 0;
        #pragma unroll
        for (int ci = 0; ci < 24; ci++) {
            unsigned long long u = cand[t * 24 + ci];
            float sv = __uint_as_float((uint32_t)(u >> 32));
            if (sv <= thr && nc < 8) cl[nc++] = (int)(u & 0xffffffffu);
        }
        float a[8][4];
        #pragma unroll
        for (int i = 0; i < 8; i++)
            #pragma unroll
            for (int p = 0; p < 4; p++) a[i][p] = 0.f;
        #pragma unroll 4
        for (int q = 0; q < 32; q++) {
            int d0 = q * 4;
            float zv0 = __ldg(zbase + (size_t)(d0 + 0) * HW + t);
            float zv1 = __ldg(zbase + (size_t)(d0 + 1) * HW + t);
            float zv2 = __ldg(zbase + (size_t)(d0 + 2) * HW + t);
            float zv3 = __ldg(zbase + (size_t)(d0 + 3) * HW + t);
            #pragma unroll
            for (int i = 0; i < 8; i++) {
                if (i < nc) {
                    float4 e4 = ((const float4*)(emb + (size_t)cl[i] * DIM))[q];
                    a[i][0] = fmaf(zv0, e4.x, a[i][0]);
                    a[i][1] = fmaf(zv1, e4.y, a[i][1]);
                    a[i][2] = fmaf(zv2, e4.z, a[i][2]);
                    a[i][3] = fmaf(zv3, e4.w, a[i][3]);
                }
            }
        }
        float z2 = z2sm[t];
        unsigned long long bestu = ~0ull;
        for (int i = 0; i < nc; i++) {
            float dot = __fadd_rn(__fadd_rn(a[i][0], a[i][1]),
                                  __fadd_rn(a[i][2], a[i][3]));
            float s = __fadd_rn(__fadd_rn(z2, e2sm[cl[i]]), __fmul_rn(-2.0f, dot));
            unsigned long long u =
                ((unsigned long long)__float_as_uint(s) << 32) | (unsigned)cl[i];
            if (u < bestu) bestu = u;
        }
        int idx = (int)(bestu & 0xffffffffu);
        idxsm[t] = idx;
        out[OFF_IDX + n0 + t] = (float)idx;
    }
    __syncthreads();

    // ---- epilogue: z_q gather+write, loss partial (z re-read coalesced) ----
    float sloc = 0.f;
    #pragma unroll 4
    for (int r = 0; r < 64; r++) {
        int linear = t + (r << 8);
        int d = linear >> 7;
        int n = linear & 127;
        float v  = emb[(size_t)idxsm[n] * DIM + d];
        float zv = __ldg(zbase + (size_t)d * HW + n);
        float diff = v - zv;
        sloc = fmaf(diff, diff, sloc);
        out[(size_t)b * (DIM * HW) + (size_t)d * HW + hw0 + n] = v;
    }
    #pragma unroll
    for (int o = 16; o; o >>= 1) sloc += __shfl_xor_sync(0xffffffffu, sloc, o);
    if (lane == 0) wsum[wid] = sloc;
    __syncthreads();
    if (t == 0) {
        float s = 0.f;
        #pragma unroll
        for (int i = 0; i < 8; i++) s += wsum[i];
        d_blockS[blk] = s;
        __threadfence();
        unsigned v = atomicAdd(&d_ctr, 1u);
        *(unsigned*)(smem + SM_FLAG) = (v == (unsigned)(gridDim.x - 1));
    }
    __syncthreads();

    // ---- last block: deterministic finalize ----
    if (*(unsigned*)(smem + SM_FLAG)) {
        float* scratch = (float*)(smem + SM_B);
        scratch[t] = d_blockS[t] + d_blockS[t + 256];
        __syncthreads();
        for (int s = 128; s > 0; s >>= 1) {
            if (t < s) scratch[t] += scratch[t + s];
            __syncthreads();
        }
        if (t == 0) {
            float S = scratch[0];
            out[OFF_LOSS]   = 1.25f * S;
            out[OFF_COMMIT] = 0.25f * S;
            out[OFF_CODE]   = S;
            d_ctr = 0;                          // reset for next graph replay
        }
    }
}

// ---------------------------------------------------------------------------
extern "C" void kernel_launch(void* const* d_in, const int* in_sizes, int n_in,
                              void* d_out, int out_size) {
    const float* z   = (const float*)d_in[0];   // (16, 128, 64, 64)
    const float* emb = (const float*)d_in[1];   // (1024, 128)
    float* out = (float*)d_out;

    cudaFuncSetAttribute(vq_main_kernel,
                         cudaFuncAttributeMaxDynamicSharedMemorySize, SMEM_BYTES);

    prep_kernel<<<128, 256>>>(emb);
    vq_main_kernel<<<NBLOCKS, 256, SMEM_BYTES>>>(z, emb, out);
}

// round 12
// speedup vs baseline: 1.4865x; 1.2259x over previous
#include <cuda_runtime.h>
#include <cstdint>

#define NUM_E   1024
#define DIM     128
#define HW      4096
#define NBLOCKS 512           // 65536 rows / 128 per CTA

// Output layout (flattened tuple, float32)
#define OFF_LOSS   8388608
#define OFF_IDX    8388609
#define OFF_COMMIT 8454145
#define OFF_CODE   8454146

#define DMARGIN 6e-4f         // margin in dot domain (score margin / 2)

__device__ float    d_enorm[NUM_E];
__device__ float    d_blockS[NBLOCKS];
// bf16 codebook in m16n8k16 B-fragment order, as 32-bit (bf16x2) words:
// [j 0..7][kg16 0..7][nb 0..7][lane 0..31][slot 0..3]
__device__ __align__(16) uint32_t d_bfrag16[65536];
__device__ unsigned d_ctr = 0;

// SMEM (byte offsets) — 103488 total, 2 CTAs/SM
#define SM_A    0          // A bf16 frag layout, 32KB
#define SM_B    32768      // B staging: 2 x 32KB j-tile buffers
#define SM_E2   98304      // 1024 f32 (raw ||e||^2, refine)
#define SM_Z2   102400     // 128 f32
#define SM_IDX  102912     // 128 i32
#define SM_WSUM 103424     // 8 f32
#define SM_FLAG 103456
#define SMEM_BYTES 103488
// cand u32[128][24] (12KB) aliases SM_B after the mainloop

static __device__ __forceinline__ uint32_t smem_u32(const void* p) {
    uint32_t a;
    asm("{ .reg .u64 t; cvta.to.shared.u64 t, %1; cvt.u32.u64 %0, t; }"
        : "=r"(a) : "l"(p));
    return a;
}
// pack two f32 -> bf16x2 (lo = first arg)
static __device__ __forceinline__ uint32_t pack_bf16x2(float lo, float hi) {
    uint32_t r;
    asm("cvt.rn.bf16x2.f32 %0, %1, %2;" : "=r"(r) : "f"(hi), "f"(lo));
    return r;
}
static __device__ __forceinline__ void mma16(float c[4], const uint32_t a[4],
                                             uint32_t b0, uint32_t b1) {
    asm("mma.sync.aligned.m16n8k16.row.col.f32.bf16.bf16.f32 "
        "{%0,%1,%2,%3}, {%4,%5,%6,%7}, {%8,%9}, {%0,%1,%2,%3};"
        : "+f"(c[0]), "+f"(c[1]), "+f"(c[2]), "+f"(c[3])
        : "r"(a[0]), "r"(a[1]), "r"(a[2]), "r"(a[3]), "r"(b0), "r"(b1));
}
static __device__ __forceinline__ void cp16(uint32_t dst, const void* src) {
    asm volatile("cp.async.cg.shared.global [%0], [%1], 16;"
                 :: "r"(dst), "l"(src) : "memory");
}
static __device__ __forceinline__ void cp_commit() {
    asm volatile("cp.async.commit_group;" ::: "memory");
}
static __device__ __forceinline__ void cp_wait1() {
    asm volatile("cp.async.wait_group 1;" ::: "memory");
}

// ---------------------------------------------------------------------------
// Prep: ||e||^2 + bf16 codebook in m16n8k16 B-fragment order.
// ---------------------------------------------------------------------------
__global__ void prep_kernel(const float* __restrict__ emb) {
    int k    = blockIdx.x * 8 + (threadIdx.x >> 5);   // code id
    int lane = threadIdx.x & 31;
    const float4* row = (const float4*)(emb + (size_t)k * DIM);
    float4 v = row[lane];
    float s = __fadd_rn(__fadd_rn(__fmul_rn(v.x, v.x), __fmul_rn(v.y, v.y)),
                        __fadd_rn(__fmul_rn(v.z, v.z), __fmul_rn(v.w, v.w)));
    #pragma unroll
    for (int o = 16; o; o >>= 1) s = __fadd_rn(s, __shfl_xor_sync(0xffffffffu, s, o));
    if (lane == 0) d_enorm[k] = s;

    int j = k >> 7, loc = k & 127;
    int nb = loc >> 4, nn = loc & 15;
    int sub = nn >> 3, g = nn & 7;
    float vv[4] = {v.x, v.y, v.z, v.w};
    #pragma unroll
    for (int w = 0; w < 2; w++) {
        int d    = lane * 4 + w * 2;
        int kg   = d >> 4;
        int half = (d >> 3) & 1;
        int tig  = (d & 7) >> 1;
        int lane_f = g * 4 + tig;
        int slot = sub * 2 + half;
        uint32_t word = pack_bf16x2(vv[w * 2], vv[w * 2 + 1]);
        d_bfrag16[((((j * 8 + kg) * 8 + nb) * 32 + lane_f) * 4) + slot] = word;
    }
}

// ---------------------------------------------------------------------------
// Main: 512 CTAs x 256 threads, 2 CTAs/SM. warp_m = wid>>1, warp_n = wid&1.
// bf16 m16n8k16; shortlist keys = u32 (dot-bits | local-id), top-3 via IMNMX.
// ---------------------------------------------------------------------------
__global__ __launch_bounds__(256, 2)
void vq_main_kernel(const float* __restrict__ z,
                    const float* __restrict__ emb,
                    float* __restrict__ out) {
    extern __shared__ char smem[];
    const uint32_t sb = smem_u32(smem);
    float* e2sm  = (float*)(smem + SM_E2);
    float* z2sm  = (float*)(smem + SM_Z2);
    int*   idxsm = (int*)(smem + SM_IDX);
    float* wsum  = (float*)(smem + SM_WSUM);

    const int t    = threadIdx.x;
    const int wid  = t >> 5;
    const int lane = t & 31;
    const int warp_m = wid >> 1;              // 0..3
    const int warp_n = wid & 1;               // 0..1
    const int blk = blockIdx.x;
    const int n0  = blk * 128;
    const int b   = n0 >> 12;
    const int hw0 = n0 & 4095;
    const float* zbase = z + (size_t)b * (DIM * HW) + hw0;
    const char*  bgb   = (const char*)d_bfrag16;

    // prefetch stages j=0,1 (full 32KB each)
    #pragma unroll
    for (int s = 0; s < 2; s++) {
        uint32_t dst = sb + SM_B + s * 32768 + t * 16;
        const char* src = bgb + s * 32768 + t * 16;
        #pragma unroll
        for (int o = 0; o < 8; o++)
            cp16(dst + o * 4096, src + o * 4096);
        cp_commit();
    }

    // e2 table (refine only)
    #pragma unroll
    for (int i = 0; i < 4; i++) e2sm[i * 256 + t] = d_enorm[i * 256 + t];

    // ---- prologue: A bf16 frags + strictly sequential z2 (z from gmem) ----
    if (t < 128) {
        const int mt = t >> 4, mm = t & 15;
        const int hm = mm >> 3, g = mm & 7;
        float z2 = 0.f;
        #pragma unroll 4
        for (int dp = 0; dp < 64; dp++) {
            int d = dp * 2;
            float v0 = __ldg(zbase + (size_t)d * HW + t);
            float v1 = __ldg(zbase + (size_t)(d + 1) * HW + t);
            z2 = __fadd_rn(__fadd_rn(z2, __fmul_rn(v0, v0)), __fmul_rn(v1, v1));
            int kg = d >> 4, half = (d >> 3) & 1, tig = (d & 7) >> 1;
            int reg = hm + 2 * half;
            int lane_f = g * 4 + tig;
            *(uint32_t*)(smem + SM_A
                + ((((kg * 8 + mt) * 32 + lane_f) * 4 + reg) << 2))
                = pack_bf16x2(v0, v1);
        }
        z2sm[t] = z2;
    }

    // top-3 max keys per pool (pool = (mf,h) row-slot)
    uint32_t kb0[4], kb1[4], kb2[4];
    #pragma unroll
    for (int i = 0; i < 4; i++) { kb0[i] = 0; kb1[i] = 0; kb2[i] = 0; }

    // ---- mainloop: 8 stages (one j-tile each) ----
    #pragma unroll 1
    for (int j = 0; j < 8; j++) {
        float acc[2][8][4];
        #pragma unroll
        for (int mf = 0; mf < 2; mf++)
            #pragma unroll
            for (int nf = 0; nf < 8; nf++)
                #pragma unroll
                for (int q = 0; q < 4; q++) acc[mf][nf][q] = 0.f;

        cp_wait1();                     // stage j data resident
        __syncthreads();                // visible to all; prior reads done

        const int bbuf = SM_B + (j & 1) * 32768;
        #pragma unroll
        for (int kg = 0; kg < 8; kg++) {
            uint4 af[2], bf[4];
            #pragma unroll
            for (int mf = 0; mf < 2; mf++)
                af[mf] = *(const uint4*)(smem + SM_A + kg * 4096
                       + (warp_m * 2 + mf) * 512 + lane * 16);
            #pragma unroll
            for (int i = 0; i < 4; i++)
                bf[i] = *(const uint4*)(smem + bbuf + kg * 4096
                      + (warp_n * 4 + i) * 512 + lane * 16);
            #pragma unroll
            for (int mf = 0; mf < 2; mf++) {
                const uint32_t* av = (const uint32_t*)&af[mf];
                #pragma unroll
                for (int i = 0; i < 4; i++) {
                    mma16(acc[mf][i * 2 + 0], av, bf[i].x, bf[i].y);
                    mma16(acc[mf][i * 2 + 1], av, bf[i].z, bf[i].w);
                }
            }
        }
        __syncthreads();                // all warps done reading buffer j&1

        if (j + 2 < 8) {                // prefetch stage j+2 into buffer j&1
            uint32_t dst = sb + SM_B + (j & 1) * 32768 + t * 16;
            const char* src = bgb + (j + 2) * 32768 + t * 16;
            #pragma unroll
            for (int o = 0; o < 8; o++)
                cp16(dst + o * 4096, src + o * 4096);
            cp_commit();
        } else {
            cp_commit();                // keep wait_group(1) accounting uniform
        }

        // shortlist scoring: key = (bits(max(dot,0)) & ~127) | local7; top-3 max
        #pragma unroll
        for (int mf = 0; mf < 2; mf++)
            #pragma unroll
            for (int nf = 0; nf < 8; nf++)
                #pragma unroll
                for (int h = 0; h < 2; h++)
                    #pragma unroll
                    for (int q = 0; q < 2; q++) {
                        float dc = fmaxf(acc[mf][nf][h * 2 + q], 0.0f);
                        uint32_t key = (__float_as_uint(dc) & 0xFFFFFF80u)
                                     | (uint32_t)((j << 4) | (nf << 1) | q);
                        int sl = mf * 2 + h;
                        uint32_t m01 = umin(key, kb0[sl]);
                        kb0[sl] = umax(key, kb0[sl]);
                        uint32_t m12 = umin(m01, kb1[sl]);
                        kb1[sl] = umax(m01, kb1[sl]);
                        kb2[sl] = umax(m12, kb2[sl]);
                    }
    }

    // ---- dump candidates: cand u32[128][24] (aliases B buffers) ----
    __syncthreads();
    uint32_t* cand = (uint32_t*)(smem + SM_B);
    {
        int ci = warp_n * 4 + (lane & 3);          // 0..7
        #pragma unroll
        for (int mf = 0; mf < 2; mf++)
            #pragma unroll
            for (int h = 0; h < 2; h++) {
                int m = warp_m * 32 + mf * 16 + h * 8 + (lane >> 2);
                int sl = mf * 2 + h;
                cand[m * 24 + ci * 3 + 0] = kb0[sl];
                cand[m * 24 + ci * 3 + 1] = kb1[sl];
                cand[m * 24 + ci * 3 + 2] = kb2[sl];
            }
    }
    __syncthreads();

    // ---- per-row: merge, margin-select, EXACT refine ----
    if (t < 128) {
        uint32_t maxk = 0; int maxci = 0;
        #pragma unroll
        for (int ci = 0; ci < 24; ci++) {
            uint32_t u = cand[t * 24 + ci];
            if (u > maxk) { maxk = u; maxci = ci; }
        }
        float dmax = __uint_as_float(maxk & 0xFFFFFF80u);
        float thrf = dmax - DMARGIN;
        uint32_t kthr = (thrf > 0.f) ? (__float_as_uint(thrf) & 0xFFFFFF80u) : 0u;

        int cl[8]; int nc = 0;
        // decode: code = j*128 + wn*64 + nf*8 + lq*2 + q  (wn=pos>>2, lq=pos&3)
        {
            int loc = maxk & 127, pos = maxci / 3;
            cl[nc++] = ((loc >> 4) << 7) + ((pos >> 2) << 6)
                     + (((loc >> 1) & 7) << 3) + ((pos & 3) << 1) + (loc & 1);
        }
        #pragma unroll
        for (int ci = 0; ci < 24; ci++) {
            uint32_t u = cand[t * 24 + ci];
            if (ci != maxci && u >= kthr && nc < 8) {
                int loc = u & 127, pos = ci / 3;
                cl[nc++] = ((loc >> 4) << 7) + ((pos >> 2) << 6)
                         + (((loc >> 1) & 7) << 3) + ((pos & 3) << 1) + (loc & 1);
            }
        }

        float a[8][4];
        #pragma unroll
        for (int i = 0; i < 8; i++)
            #pragma unroll
            for (int p = 0; p < 4; p++) a[i][p] = 0.f;
        #pragma unroll 4
        for (int q = 0; q < 32; q++) {
            int d0 = q * 4;
            float zv0 = __ldg(zbase + (size_t)(d0 + 0) * HW + t);
            float zv1 = __ldg(zbase + (size_t)(d0 + 1) * HW + t);
            float zv2 = __ldg(zbase + (size_t)(d0 + 2) * HW + t);
            float zv3 = __ldg(zbase + (size_t)(d0 + 3) * HW + t);
            #pragma unroll
            for (int i = 0; i < 8; i++) {
                if (i < nc) {
                    float4 e4 = ((const float4*)(emb + (size_t)cl[i] * DIM))[q];
                    a[i][0] = fmaf(zv0, e4.x, a[i][0]);
                    a[i][1] = fmaf(zv1, e4.y, a[i][1]);
                    a[i][2] = fmaf(zv2, e4.z, a[i][2]);
                    a[i][3] = fmaf(zv3, e4.w, a[i][3]);
                }
            }
        }
        float z2 = z2sm[t];
        unsigned long long bestu = ~0ull;
        for (int i = 0; i < nc; i++) {
            float dot = __fadd_rn(__fadd_rn(a[i][0], a[i][1]),
                                  __fadd_rn(a[i][2], a[i][3]));
            float s = __fadd_rn(__fadd_rn(z2, e2sm[cl[i]]), __fmul_rn(-2.0f, dot));
            unsigned long long u =
                ((unsigned long long)__float_as_uint(s) << 32) | (unsigned)cl[i];
            if (u < bestu) bestu = u;
        }
        int idx = (int)(bestu & 0xffffffffu);
        idxsm[t] = idx;
        out[OFF_IDX + n0 + t] = (float)idx;
    }
    __syncthreads();

    // ---- epilogue: z_q gather+write, loss partial (z re-read coalesced) ----
    float sloc = 0.f;
    #pragma unroll 4
    for (int r = 0; r < 64; r++) {
        int linear = t + (r << 8);
        int d = linear >> 7;
        int n = linear & 127;
        float v  = emb[(size_t)idxsm[n] * DIM + d];
        float zv = __ldg(zbase + (size_t)d * HW + n);
        float diff = v - zv;
        sloc = fmaf(diff, diff, sloc);
        out[(size_t)b * (DIM * HW) + (size_t)d * HW + hw0 + n] = v;
    }
    #pragma unroll
    for (int o = 16; o; o >>= 1) sloc += __shfl_xor_sync(0xffffffffu, sloc, o);
    if (lane == 0) wsum[wid] = sloc;
    __syncthreads();
    if (t == 0) {
        float s = 0.f;
        #pragma unroll
        for (int i = 0; i < 8; i++) s += wsum[i];
        d_blockS[blk] = s;
        __threadfence();
        unsigned v = atomicAdd(&d_ctr, 1u);
        *(unsigned*)(smem + SM_FLAG) = (v == (unsigned)(gridDim.x - 1));
    }
    __syncthreads();

    // ---- last block: deterministic finalize ----
    if (*(unsigned*)(smem + SM_FLAG)) {
        float* scratch = (float*)(smem + SM_B);
        scratch[t] = d_blockS[t] + d_blockS[t + 256];
        __syncthreads();
        for (int s = 128; s > 0; s >>= 1) {
            if (t < s) scratch[t] += scratch[t + s];
            __syncthreads();
        }
        if (t == 0) {
            float S = scratch[0];
            out[OFF_LOSS]   = 1.25f * S;
            out[OFF_COMMIT] = 0.25f * S;
            out[OFF_CODE]   = S;
            d_ctr = 0;                          // reset for next graph replay
        }
    }
}

// ---------------------------------------------------------------------------
extern "C" void kernel_launch(void* const* d_in, const int* in_sizes, int n_in,
                              void* d_out, int out_size) {
    const float* z   = (const float*)d_in[0];   // (16, 128, 64, 64)
    const float* emb = (const float*)d_in[1];   // (1024, 128)
    float* out = (float*)d_out;

    cudaFuncSetAttribute(vq_main_kernel,
                         cudaFuncAttributeMaxDynamicSharedMemorySize, SMEM_BYTES);

    prep_kernel<<<128, 256>>>(emb);
    vq_main_kernel<<<NBLOCKS, 256, SMEM_BYTES>>>(z, emb, out);
}

// round 13
// speedup vs baseline: 1.5580x; 1.0481x over previous
#include <cuda_runtime.h>
#include <cstdint>

#define NUM_E   1024
#define DIM     128
#define HW      4096
#define NTILES  512           // 65536 rows / 128 per tile
#define GRID    304           // 2 per SM (152 SMs on GB300)
#define LASTV   (NTILES + GRID - 1)   // final atomicAdd return value per replay

// Output layout (flattened tuple, float32)
#define OFF_LOSS   8388608
#define OFF_IDX    8388609
#define OFF_COMMIT 8454145
#define OFF_CODE   8454146

#define DMARGIN 6e-4f         // margin in dot domain

__device__ float    d_enorm[NUM_E];
__device__ float    d_blockS[NTILES];
// bf16 codebook in m16n8k16 B-fragment order, as 32-bit (bf16x2) words:
// [s=j*8+kg 0..63][nb 0..7][lane 0..31][slot 0..3]
__device__ __align__(16) uint32_t d_bfrag16[65536];
__device__ unsigned d_tile = 0;

// SMEM (byte offsets)
#define SM_A    0          // A bf16 frag layout, 32KB
#define SM_CAND 32768      // cand u32[128][24], 12KB (finalize scratch aliases)
#define SM_E2   45056      // 1024 f32
#define SM_Z2   49152      // 128 f32
#define SM_IDX  49664      // 128 i32
#define SM_WSUM 50176      // 8 f32
#define SM_TILE 50208      // 1 i32
#define SMEM_BYTES 50240

static __device__ __forceinline__ uint32_t pack_bf16x2(float lo, float hi) {
    uint32_t r;
    asm("cvt.rn.bf16x2.f32 %0, %1, %2;" : "=r"(r) : "f"(hi), "f"(lo));
    return r;
}
static __device__ __forceinline__ void mma16(float c[4], const uint32_t a[4],
                                             uint32_t b0, uint32_t b1) {
    asm("mma.sync.aligned.m16n8k16.row.col.f32.bf16.bf16.f32 "
        "{%0,%1,%2,%3}, {%4,%5,%6,%7}, {%8,%9}, {%0,%1,%2,%3};"
        : "+f"(c[0]), "+f"(c[1]), "+f"(c[2]), "+f"(c[3])
        : "r"(a[0]), "r"(a[1]), "r"(a[2]), "r"(a[3]), "r"(b0), "r"(b1));
}

// ---------------------------------------------------------------------------
// Prep: ||e||^2 + bf16 codebook in m16n8k16 B-fragment order.
// ---------------------------------------------------------------------------
__global__ void prep_kernel(const float* __restrict__ emb) {
    int k    = blockIdx.x * 8 + (threadIdx.x >> 5);   // code id
    int lane = threadIdx.x & 31;
    const float4* row = (const float4*)(emb + (size_t)k * DIM);
    float4 v = row[lane];
    float s = __fadd_rn(__fadd_rn(__fmul_rn(v.x, v.x), __fmul_rn(v.y, v.y)),
                        __fadd_rn(__fmul_rn(v.z, v.z), __fmul_rn(v.w, v.w)));
    #pragma unroll
    for (int o = 16; o; o >>= 1) s = __fadd_rn(s, __shfl_xor_sync(0xffffffffu, s, o));
    if (lane == 0) d_enorm[k] = s;

    int j = k >> 7, loc = k & 127;
    int nb = loc >> 4, nn = loc & 15;
    int sub = nn >> 3, g = nn & 7;
    float vv[4] = {v.x, v.y, v.z, v.w};
    #pragma unroll
    for (int w = 0; w < 2; w++) {
        int d    = lane * 4 + w * 2;
        int kg   = d >> 4;
        int half = (d >> 3) & 1;
        int tig  = (d & 7) >> 1;
        int lane_f = g * 4 + tig;
        int slot = sub * 2 + half;
        uint32_t word = pack_bf16x2(vv[w * 2], vv[w * 2 + 1]);
        d_bfrag16[((((j * 8 + kg) * 8 + nb) * 32 + lane_f) * 4) + slot] = word;
    }
}

// ---------------------------------------------------------------------------
// Main: persistent, GRID x 256 threads, 2 CTAs/SM, dynamic tile stealing.
// bf16 m16n8k16; B frags streamed by direct __ldg (no staging, no barriers
// in the mainloop); shortlist keys u32; exact fp32 refine.
// ---------------------------------------------------------------------------
__global__ __launch_bounds__(256, 2)
void vq_main_kernel(const float* __restrict__ z,
                    const float* __restrict__ emb,
                    float* __restrict__ out) {
    extern __shared__ char smem[];
    float* e2sm  = (float*)(smem + SM_E2);
    float* z2sm  = (float*)(smem + SM_Z2);
    int*   idxsm = (int*)(smem + SM_IDX);
    float* wsum  = (float*)(smem + SM_WSUM);
    int*   stile = (int*)(smem + SM_TILE);
    uint32_t* cand = (uint32_t*)(smem + SM_CAND);

    const int t    = threadIdx.x;
    const int wid  = t >> 5;
    const int lane = t & 31;
    const int warp_m = wid >> 1;              // 0..3
    const int warp_n = wid & 1;               // 0..1
    const char* bgb = (const char*)d_bfrag16;

    // e2 table (persists across tiles)
    #pragma unroll
    for (int i = 0; i < 4; i++) e2sm[i * 256 + t] = d_enorm[i * 256 + t];

    // persistent B ring: preload s=0 into buffer 0
    uint4 bfr[2][4];
    {
        const char* pb = bgb + ((warp_n << 2) << 9) + (lane << 4);
        #pragma unroll
        for (int i = 0; i < 4; i++)
            bfr[0][i] = __ldg((const uint4*)(pb + (i << 9)));
    }

    int vtile;
    while (true) {
        __syncthreads();                       // smem reuse fence (A, cand, stile)
        if (t == 0) *stile = (int)atomicAdd(&d_tile, 1u);
        __syncthreads();
        vtile = *stile;
        if (vtile >= NTILES) break;
        const int tile = vtile;
        const int n0  = tile * 128;
        const int b   = n0 >> 12;
        const int hw0 = n0 & 4095;
        const float* zbase = z + (size_t)b * (DIM * HW) + hw0;

        // ---- prologue: A bf16 frags + strictly sequential z2 ----
        if (t < 128) {
            const int mt = t >> 4, mm = t & 15;
            const int hm = mm >> 3, g = mm & 7;
            float z2 = 0.f;
            #pragma unroll 4
            for (int dp = 0; dp < 64; dp++) {
                int d = dp * 2;
                float v0 = __ldg(zbase + (size_t)d * HW + t);
                float v1 = __ldg(zbase + (size_t)(d + 1) * HW + t);
                z2 = __fadd_rn(__fadd_rn(z2, __fmul_rn(v0, v0)), __fmul_rn(v1, v1));
                int kg = d >> 4, half = (d >> 3) & 1, tig = (d & 7) >> 1;
                int reg = hm + 2 * half;
                int lane_f = g * 4 + tig;
                *(uint32_t*)(smem + SM_A
                    + ((((kg * 8 + mt) * 32 + lane_f) * 4 + reg) << 2))
                    = pack_bf16x2(v0, v1);
            }
            z2sm[t] = z2;
        }
        __syncthreads();

        // top-3 max keys per pool (pool = (mf,h) row-slot)
        uint32_t kb0[4], kb1[4], kb2[4];
        #pragma unroll
        for (int i = 0; i < 4; i++) { kb0[i] = 0; kb1[i] = 0; kb2[i] = 0; }

        // ---- mainloop: barrier-free; B via direct LDG ring ----
        #pragma unroll 1
        for (int j = 0; j < 8; j++) {
            float acc[2][8][4];
            #pragma unroll
            for (int mf = 0; mf < 2; mf++)
                #pragma unroll
                for (int nf = 0; nf < 8; nf++)
                    #pragma unroll
                    for (int q = 0; q < 4; q++) acc[mf][nf][q] = 0.f;

            #pragma unroll
            for (int kg = 0; kg < 8; kg++) {
                // prefetch next s (wraps; B is tile-invariant so wrap is valid)
                {
                    int sn = (j * 8 + kg + 1) & 63;
                    const char* pb = bgb + (((sn << 3) + (warp_n << 2)) << 9)
                                   + (lane << 4);
                    #pragma unroll
                    for (int i = 0; i < 4; i++)
                        bfr[(kg + 1) & 1][i] = __ldg((const uint4*)(pb + (i << 9)));
                }
                uint4 af[2];
                #pragma unroll
                for (int mf = 0; mf < 2; mf++)
                    af[mf] = *(const uint4*)(smem + SM_A + kg * 4096
                           + (warp_m * 2 + mf) * 512 + lane * 16);
                const uint4* bc = bfr[kg & 1];
                #pragma unroll
                for (int mf = 0; mf < 2; mf++) {
                    const uint32_t* av = (const uint32_t*)&af[mf];
                    #pragma unroll
                    for (int i = 0; i < 4; i++) {
                        mma16(acc[mf][i * 2 + 0], av, bc[i].x, bc[i].y);
                        mma16(acc[mf][i * 2 + 1], av, bc[i].z, bc[i].w);
                    }
                }
            }

            // shortlist scoring: key = (bits(max(dot,0)) & ~127) | local7
            #pragma unroll
            for (int mf = 0; mf < 2; mf++)
                #pragma unroll
                for (int nf = 0; nf < 8; nf++)
                    #pragma unroll
                    for (int h = 0; h < 2; h++)
                        #pragma unroll
                        for (int q = 0; q < 2; q++) {
                            float dc = fmaxf(acc[mf][nf][h * 2 + q], 0.0f);
                            uint32_t key = (__float_as_uint(dc) & 0xFFFFFF80u)
                                         | (uint32_t)((j << 4) | (nf << 1) | q);
                            int sl = mf * 2 + h;
                            uint32_t m01 = umin(key, kb0[sl]);
                            kb0[sl] = umax(key, kb0[sl]);
                            uint32_t m12 = umin(m01, kb1[sl]);
                            kb1[sl] = umax(m01, kb1[sl]);
                            kb2[sl] = umax(m12, kb2[sl]);
                        }
        }

        // ---- dump candidates: cand u32[128][24] ----
        __syncthreads();
        {
            int ci = warp_n * 4 + (lane & 3);          // 0..7
            #pragma unroll
            for (int mf = 0; mf < 2; mf++)
                #pragma unroll
                for (int h = 0; h < 2; h++) {
                    int m = warp_m * 32 + mf * 16 + h * 8 + (lane >> 2);
                    int sl = mf * 2 + h;
                    cand[m * 24 + ci * 3 + 0] = kb0[sl];
                    cand[m * 24 + ci * 3 + 1] = kb1[sl];
                    cand[m * 24 + ci * 3 + 2] = kb2[sl];
                }
        }
        __syncthreads();

        // ---- per-row: merge, margin-select, EXACT refine ----
        if (t < 128) {
            uint32_t maxk = 0; int maxci = 0;
            #pragma unroll
            for (int ci = 0; ci < 24; ci++) {
                uint32_t u = cand[t * 24 + ci];
                if (u > maxk) { maxk = u; maxci = ci; }
            }
            float dmax = __uint_as_float(maxk & 0xFFFFFF80u);
            float thrf = dmax - DMARGIN;
            uint32_t kthr = (thrf > 0.f) ? (__float_as_uint(thrf) & 0xFFFFFF80u) : 0u;

            int cl[8]; int nc = 0;
            {
                int loc = maxk & 127, pos = maxci / 3;
                cl[nc++] = ((loc >> 4) << 7) + ((pos >> 2) << 6)
                         + (((loc >> 1) & 7) << 3) + ((pos & 3) << 1) + (loc & 1);
            }
            #pragma unroll
            for (int ci = 0; ci < 24; ci++) {
                uint32_t u = cand[t * 24 + ci];
                if (ci != maxci && u >= kthr && nc < 8) {
                    int loc = u & 127, pos = ci / 3;
                    cl[nc++] = ((loc >> 4) << 7) + ((pos >> 2) << 6)
                             + (((loc >> 1) & 7) << 3) + ((pos & 3) << 1) + (loc & 1);
                }
            }

            float a[8][4];
            #pragma unroll
            for (int i = 0; i < 8; i++)
                #pragma unroll
                for (int p = 0; p < 4; p++) a[i][p] = 0.f;
            #pragma unroll 4
            for (int q = 0; q < 32; q++) {
                int d0 = q * 4;
                float zv0 = __ldg(zbase + (size_t)(d0 + 0) * HW + t);
                float zv1 = __ldg(zbase + (size_t)(d0 + 1) * HW + t);
                float zv2 = __ldg(zbase + (size_t)(d0 + 2) * HW + t);
                float zv3 = __ldg(zbase + (size_t)(d0 + 3) * HW + t);
                #pragma unroll
                for (int i = 0; i < 8; i++) {
                    if (i < nc) {
                        float4 e4 = ((const float4*)(emb + (size_t)cl[i] * DIM))[q];
                        a[i][0] = fmaf(zv0, e4.x, a[i][0]);
                        a[i][1] = fmaf(zv1, e4.y, a[i][1]);
                        a[i][2] = fmaf(zv2, e4.z, a[i][2]);
                        a[i][3] = fmaf(zv3, e4.w, a[i][3]);
                    }
                }
            }
            float z2 = z2sm[t];
            unsigned long long bestu = ~0ull;
            for (int i = 0; i < nc; i++) {
                float dot = __fadd_rn(__fadd_rn(a[i][0], a[i][1]),
                                      __fadd_rn(a[i][2], a[i][3]));
                float s = __fadd_rn(__fadd_rn(z2, e2sm[cl[i]]),
                                    __fmul_rn(-2.0f, dot));
                unsigned long long u =
                    ((unsigned long long)__float_as_uint(s) << 32) | (unsigned)cl[i];
                if (u < bestu) bestu = u;
            }
            int idx = (int)(bestu & 0xffffffffu);
            idxsm[t] = idx;
            out[OFF_IDX + n0 + t] = (float)idx;
        }
        __syncthreads();

        // ---- epilogue: z_q gather+write, loss partial ----
        float sloc = 0.f;
        #pragma unroll 4
        for (int r = 0; r < 64; r++) {
            int linear = t + (r << 8);
            int d = linear >> 7;
            int n = linear & 127;
            float v  = emb[(size_t)idxsm[n] * DIM + d];
            float zv = __ldg(zbase + (size_t)d * HW + n);
            float diff = v - zv;
            sloc = fmaf(diff, diff, sloc);
            out[(size_t)b * (DIM * HW) + (size_t)d * HW + hw0 + n] = v;
        }
        #pragma unroll
        for (int o = 16; o; o >>= 1) sloc += __shfl_xor_sync(0xffffffffu, sloc, o);
        if (lane == 0) wsum[wid] = sloc;
        __syncthreads();
        if (t == 0) {
            float s = 0.f;
            #pragma unroll
            for (int i = 0; i < 8; i++) s += wsum[i];
            d_blockS[tile] = s;
            __threadfence();        // blockS visible before our next atomicAdd
        }
    }

    // ---- overshoot: the CTA whose grab returned LASTV finalizes + resets ----
    if (vtile == LASTV) {
        float* scratch = (float*)(smem + SM_CAND);
        scratch[t] = d_blockS[t] + d_blockS[t + 256];
        __syncthreads();
        for (int s = 128; s > 0; s >>= 1) {
            if (t < s) scratch[t] += scratch[t + s];
            __syncthreads();
        }
        if (t == 0) {
            float S = scratch[0];
            out[OFF_LOSS]   = 1.25f * S;
            out[OFF_COMMIT] = 0.25f * S;
            out[OFF_CODE]   = S;
            d_tile = 0;                         // last atomic user: safe reset
        }
    }
}

// ---------------------------------------------------------------------------
extern "C" void kernel_launch(void* const* d_in, const int* in_sizes, int n_in,
                              void* d_out, int out_size) {
    const float* z   = (const float*)d_in[0];   // (16, 128, 64, 64)
    const float* emb = (const float*)d_in[1];   // (1024, 128)
    float* out = (float*)d_out;

    cudaFuncSetAttribute(vq_main_kernel,
                         cudaFuncAttributeMaxDynamicSharedMemorySize, SMEM_BYTES);

    prep_kernel<<<128, 256>>>(emb);
    vq_main_kernel<<<GRID, 256, SMEM_BYTES>>>(z, emb, out);
}

// round 14
// speedup vs baseline: 1.6397x; 1.0525x over previous
#include <cuda_runtime.h>
#include <cstdint>

#define NUM_E   1024
#define DIM     128
#define HW      4096
#define NTILES  512           // 65536 rows / 128 per tile
#define GRID    304           // 2 per SM (152 SMs on GB300)
#define LASTV   (NTILES + GRID - 1)   // final atomicAdd return value per replay

// Output layout (flattened tuple, float32)
#define OFF_LOSS   8388608
#define OFF_IDX    8388609
#define OFF_COMMIT 8454145
#define OFF_CODE   8454146

#define DMARGIN 6e-4f         // margin in dot domain

__device__ float    d_enorm[NUM_E];
__device__ float    d_blockS[NTILES];
// bf16 codebook in m16n8k16 B-fragment order, as 32-bit (bf16x2) words:
// [s=j*8+kg 0..63][nb 0..7][lane 0..31][slot 0..3]
__device__ __align__(16) uint32_t d_bfrag16[65536];
__device__ unsigned d_tile = 0;

// SMEM (byte offsets), ~101KB -> 2 CTAs/SM
#define SM_A    0          // A bf16 frag layout, 32KB (mainloop only)
#define SM_ZPL  32768      // z tile f32 [d][n], 64KB
#define SM_CAND 0          // cand u32[128][24], 12KB — aliases A post-mainloop
#define SM_RB   16384      // refine best u64[2][128], 2KB — aliases A
#define SM_E2   98304      // 1024 f32
#define SM_Z2   102400     // 128 f32
#define SM_IDX  102912     // 128 i32
#define SM_WSUM 103424     // 8 f32
#define SM_TILE 103456     // 1 i32
#define SMEM_BYTES 103488

static __device__ __forceinline__ uint32_t pack_bf16x2(float lo, float hi) {
    uint32_t r;
    asm("cvt.rn.bf16x2.f32 %0, %1, %2;" : "=r"(r) : "f"(hi), "f"(lo));
    return r;
}
static __device__ __forceinline__ void mma16(float c[4], const uint32_t a[4],
                                             uint32_t b0, uint32_t b1) {
    asm("mma.sync.aligned.m16n8k16.row.col.f32.bf16.bf16.f32 "
        "{%0,%1,%2,%3}, {%4,%5,%6,%7}, {%8,%9}, {%0,%1,%2,%3};"
        : "+f"(c[0]), "+f"(c[1]), "+f"(c[2]), "+f"(c[3])
        : "r"(a[0]), "r"(a[1]), "r"(a[2]), "r"(a[3]), "r"(b0), "r"(b1));
}

// ---------------------------------------------------------------------------
// Prep: ||e||^2 + bf16 codebook in m16n8k16 B-fragment order.
// ---------------------------------------------------------------------------
__global__ void prep_kernel(const float* __restrict__ emb) {
    int k    = blockIdx.x * 8 + (threadIdx.x >> 5);   // code id
    int lane = threadIdx.x & 31;
    const float4* row = (const float4*)(emb + (size_t)k * DIM);
    float4 v = row[lane];
    float s = __fadd_rn(__fadd_rn(__fmul_rn(v.x, v.x), __fmul_rn(v.y, v.y)),
                        __fadd_rn(__fmul_rn(v.z, v.z), __fmul_rn(v.w, v.w)));
    #pragma unroll
    for (int o = 16; o; o >>= 1) s = __fadd_rn(s, __shfl_xor_sync(0xffffffffu, s, o));
    if (lane == 0) d_enorm[k] = s;

    int j = k >> 7, loc = k & 127;
    int nb = loc >> 4, nn = loc & 15;
    int sub = nn >> 3, g = nn & 7;
    float vv[4] = {v.x, v.y, v.z, v.w};
    #pragma unroll
    for (int w = 0; w < 2; w++) {
        int d    = lane * 4 + w * 2;
        int kg   = d >> 4;
        int half = (d >> 3) & 1;
        int tig  = (d & 7) >> 1;
        int lane_f = g * 4 + tig;
        int slot = sub * 2 + half;
        uint32_t word = pack_bf16x2(vv[w * 2], vv[w * 2 + 1]);
        d_bfrag16[((((j * 8 + kg) * 8 + nb) * 32 + lane_f) * 4) + slot] = word;
    }
}

// ---------------------------------------------------------------------------
// Main: persistent, GRID x 256, 2 CTAs/SM, dynamic tile stealing.
// bf16 m16n8k16; B via direct __ldg ring (no mainloop barriers);
// z tile cached in SMEM; refine split 2-way per row; exact fp32 refine.
// ---------------------------------------------------------------------------
__global__ __launch_bounds__(256, 2)
void vq_main_kernel(const float* __restrict__ z,
                    const float* __restrict__ emb,
                    float* __restrict__ out) {
    extern __shared__ char smem[];
    float* zpl   = (float*)(smem + SM_ZPL);
    float* e2sm  = (float*)(smem + SM_E2);
    float* z2sm  = (float*)(smem + SM_Z2);
    int*   idxsm = (int*)(smem + SM_IDX);
    float* wsum  = (float*)(smem + SM_WSUM);
    int*   stile = (int*)(smem + SM_TILE);
    uint32_t* cand = (uint32_t*)(smem + SM_CAND);
    unsigned long long* rbest = (unsigned long long*)(smem + SM_RB);

    const int t    = threadIdx.x;
    const int wid  = t >> 5;
    const int lane = t & 31;
    const int warp_m = wid >> 1;              // 0..3
    const int warp_n = wid & 1;               // 0..1
    const char* bgb = (const char*)d_bfrag16;

    // e2 table (persists across tiles)
    #pragma unroll
    for (int i = 0; i < 4; i++) e2sm[i * 256 + t] = d_enorm[i * 256 + t];

    // persistent B ring: preload s=0 into buffer 0
    uint4 bfr[2][4];
    {
        const char* pb = bgb + ((warp_n << 2) << 9) + (lane << 4);
        #pragma unroll
        for (int i = 0; i < 4; i++)
            bfr[0][i] = __ldg((const uint4*)(pb + (i << 9)));
    }

    int vtile;
    while (true) {
        __syncthreads();                       // smem reuse fence
        if (t == 0) *stile = (int)atomicAdd(&d_tile, 1u);
        __syncthreads();
        vtile = *stile;
        if (vtile >= NTILES) break;
        const int tile = vtile;
        const int n0  = tile * 128;
        const int b   = n0 >> 12;
        const int hw0 = n0 & 4095;
        const float* zbase = z + (size_t)b * (DIM * HW) + hw0;

        // ---- prologue A: fill zpl (coalesced float4, all 256 threads) ----
        #pragma unroll
        for (int i = 0; i < 16; i++) {
            int id = t + 256 * i;              // 4096 float4 = 128d x 128n
            int dl = id >> 5, hw4 = (id & 31) * 4;
            float4 v = *(const float4*)(zbase + (size_t)dl * HW + hw4);
            *(float4*)(&zpl[dl * 128 + hw4]) = v;
        }
        __syncthreads();

        // ---- prologue B: A bf16 frags + strictly sequential z2 (from zpl) ----
        if (t < 128) {
            const int mt = t >> 4, mm = t & 15;
            const int hm = mm >> 3, g = mm & 7;
            float z2 = 0.f;
            #pragma unroll 4
            for (int dp = 0; dp < 64; dp++) {
                int d = dp * 2;
                float v0 = zpl[d * 128 + t];
                float v1 = zpl[(d + 1) * 128 + t];
                z2 = __fadd_rn(__fadd_rn(z2, __fmul_rn(v0, v0)), __fmul_rn(v1, v1));
                int kg = d >> 4, half = (d >> 3) & 1, tig = (d & 7) >> 1;
                int reg = hm + 2 * half;
                int lane_f = g * 4 + tig;
                *(uint32_t*)(smem + SM_A
                    + ((((kg * 8 + mt) * 32 + lane_f) * 4 + reg) << 2))
                    = pack_bf16x2(v0, v1);
            }
            z2sm[t] = z2;
        }
        __syncthreads();

        // top-3 max keys per pool (pool = (mf,h) row-slot)
        uint32_t kb0[4], kb1[4], kb2[4];
        #pragma unroll
        for (int i = 0; i < 4; i++) { kb0[i] = 0; kb1[i] = 0; kb2[i] = 0; }

        // ---- mainloop: barrier-free; B via direct LDG ring ----
        #pragma unroll 1
        for (int j = 0; j < 8; j++) {
            float acc[2][8][4];
            #pragma unroll
            for (int mf = 0; mf < 2; mf++)
                #pragma unroll
                for (int nf = 0; nf < 8; nf++)
                    #pragma unroll
                    for (int q = 0; q < 4; q++) acc[mf][nf][q] = 0.f;

            #pragma unroll
            for (int kg = 0; kg < 8; kg++) {
                {   // prefetch next s (wraps; B tile-invariant so wrap valid)
                    int sn = (j * 8 + kg + 1) & 63;
                    const char* pb = bgb + (((sn << 3) + (warp_n << 2)) << 9)
                                   + (lane << 4);
                    #pragma unroll
                    for (int i = 0; i < 4; i++)
                        bfr[(kg + 1) & 1][i] = __ldg((const uint4*)(pb + (i << 9)));
                }
                uint4 af[2];
                #pragma unroll
                for (int mf = 0; mf < 2; mf++)
                    af[mf] = *(const uint4*)(smem + SM_A + kg * 4096
                           + (warp_m * 2 + mf) * 512 + lane * 16);
                const uint4* bc = bfr[kg & 1];
                #pragma unroll
                for (int mf = 0; mf < 2; mf++) {
                    const uint32_t* av = (const uint32_t*)&af[mf];
                    #pragma unroll
                    for (int i = 0; i < 4; i++) {
                        mma16(acc[mf][i * 2 + 0], av, bc[i].x, bc[i].y);
                        mma16(acc[mf][i * 2 + 1], av, bc[i].z, bc[i].w);
                    }
                }
            }

            // shortlist scoring: key = (bits(max(dot,0)) & ~127) | local7
            #pragma unroll
            for (int mf = 0; mf < 2; mf++)
                #pragma unroll
                for (int nf = 0; nf < 8; nf++)
                    #pragma unroll
                    for (int h = 0; h < 2; h++)
                        #pragma unroll
                        for (int q = 0; q < 2; q++) {
                            float dc = fmaxf(acc[mf][nf][h * 2 + q], 0.0f);
                            uint32_t key = (__float_as_uint(dc) & 0xFFFFFF80u)
                                         | (uint32_t)((j << 4) | (nf << 1) | q);
                            int sl = mf * 2 + h;
                            uint32_t m01 = umin(key, kb0[sl]);
                            kb0[sl] = umax(key, kb0[sl]);
                            uint32_t m12 = umin(m01, kb1[sl]);
                            kb1[sl] = umax(m01, kb1[sl]);
                            kb2[sl] = umax(m12, kb2[sl]);
                        }
        }

        // ---- dump candidates: cand u32[128][24] (aliases A frags) ----
        __syncthreads();
        {
            int ci = warp_n * 4 + (lane & 3);          // 0..7
            #pragma unroll
            for (int mf = 0; mf < 2; mf++)
                #pragma unroll
                for (int h = 0; h < 2; h++) {
                    int m = warp_m * 32 + mf * 16 + h * 8 + (lane >> 2);
                    int sl = mf * 2 + h;
                    cand[m * 24 + ci * 3 + 0] = kb0[sl];
                    cand[m * 24 + ci * 3 + 1] = kb1[sl];
                    cand[m * 24 + ci * 3 + 2] = kb2[sl];
                }
        }
        __syncthreads();

        // ---- refine: 2 threads per row (t: ci 0..11, t+128: ci 12..23) ----
        {
            const int row  = t & 127;
            const int half = t >> 7;

            uint32_t maxk = 0;
            #pragma unroll
            for (int ci = 0; ci < 24; ci++) {
                uint32_t u = cand[row * 24 + ci];
                if (u > maxk) maxk = u;
            }
            float dmax = __uint_as_float(maxk & 0xFFFFFF80u);
            float thrf = dmax - DMARGIN;
            uint32_t kthr = (thrf > 0.f) ? (__float_as_uint(thrf) & 0xFFFFFF80u) : 0u;

            int cl[8]; int nc = 0;
            #pragma unroll
            for (int ci = 0; ci < 12; ci++) {
                int cig = half * 12 + ci;
                uint32_t u = cand[row * 24 + cig];
                if (u >= kthr && nc < 8) {
                    int loc = u & 127, pos = cig / 3;
                    cl[nc++] = ((loc >> 4) << 7) + ((pos >> 2) << 6)
                             + (((loc >> 1) & 7) << 3) + ((pos & 3) << 1) + (loc & 1);
                }
            }

            float a[8][4];
            #pragma unroll
            for (int i = 0; i < 8; i++)
                #pragma unroll
                for (int p = 0; p < 4; p++) a[i][p] = 0.f;
            #pragma unroll 4
            for (int q = 0; q < 32; q++) {
                int d0 = q * 4;
                float zv0 = zpl[(d0 + 0) * 128 + row];
                float zv1 = zpl[(d0 + 1) * 128 + row];
                float zv2 = zpl[(d0 + 2) * 128 + row];
                float zv3 = zpl[(d0 + 3) * 128 + row];
                #pragma unroll
                for (int i = 0; i < 8; i++) {
                    if (i < nc) {
                        float4 e4 = ((const float4*)(emb + (size_t)cl[i] * DIM))[q];
                        a[i][0] = fmaf(zv0, e4.x, a[i][0]);
                        a[i][1] = fmaf(zv1, e4.y, a[i][1]);
                        a[i][2] = fmaf(zv2, e4.z, a[i][2]);
                        a[i][3] = fmaf(zv3, e4.w, a[i][3]);
                    }
                }
            }
            float z2 = z2sm[row];
            unsigned long long bestu = ~0ull;
            for (int i = 0; i < nc; i++) {
                float dot = __fadd_rn(__fadd_rn(a[i][0], a[i][1]),
                                      __fadd_rn(a[i][2], a[i][3]));
                float s = __fadd_rn(__fadd_rn(z2, e2sm[cl[i]]),
                                    __fmul_rn(-2.0f, dot));
                unsigned long long u =
                    ((unsigned long long)__float_as_uint(s) << 32) | (unsigned)cl[i];
                if (u < bestu) bestu = u;
            }
            rbest[half * 128 + row] = bestu;
        }
        __syncthreads();
        if (t < 128) {
            unsigned long long u0 = rbest[t];
            unsigned long long u1 = rbest[128 + t];
            unsigned long long bu = (u0 < u1) ? u0 : u1;
            int idx = (int)(bu & 0xffffffffu);
            idxsm[t] = idx;
            out[OFF_IDX + n0 + t] = (float)idx;
        }
        __syncthreads();

        // ---- epilogue: z_q gather+write, loss partial (z from SMEM) ----
        float sloc = 0.f;
        #pragma unroll 4
        for (int r = 0; r < 64; r++) {
            int linear = t + (r << 8);
            int d = linear >> 7;
            int n = linear & 127;
            float v  = emb[(size_t)idxsm[n] * DIM + d];
            float zv = zpl[d * 128 + n];
            float diff = v - zv;
            sloc = fmaf(diff, diff, sloc);
            out[(size_t)b * (DIM * HW) + (size_t)d * HW + hw0 + n] = v;
        }
        #pragma unroll
        for (int o = 16; o; o >>= 1) sloc += __shfl_xor_sync(0xffffffffu, sloc, o);
        if (lane == 0) wsum[wid] = sloc;
        __syncthreads();
        if (t == 0) {
            float s = 0.f;
            #pragma unroll
            for (int i = 0; i < 8; i++) s += wsum[i];
            d_blockS[tile] = s;
            __threadfence();        // blockS visible before our next atomicAdd
        }
    }

    // ---- overshoot: the CTA whose grab returned LASTV finalizes + resets ----
    if (vtile == LASTV) {
        float* scratch = (float*)(smem + SM_CAND);
        scratch[t] = d_blockS[t] + d_blockS[t + 256];
        __syncthreads();
        for (int s = 128; s > 0; s >>= 1) {
            if (t < s) scratch[t] += scratch[t + s];
            __syncthreads();
        }
        if (t == 0) {
            float S = scratch[0];
            out[OFF_LOSS]   = 1.25f * S;
            out[OFF_COMMIT] = 0.25f * S;
            out[OFF_CODE]   = S;
            d_tile = 0;                         // last atomic user: safe reset
        }
    }
}

// ---------------------------------------------------------------------------
extern "C" void kernel_launch(void* const* d_in, const int* in_sizes, int n_in,
                              void* d_out, int out_size) {
    const float* z   = (const float*)d_in[0];   // (16, 128, 64, 64)
    const float* emb = (const float*)d_in[1];   // (1024, 128)
    float* out = (float*)d_out;

    cudaFuncSetAttribute(vq_main_kernel,
                         cudaFuncAttributeMaxDynamicSharedMemorySize, SMEM_BYTES);

    prep_kernel<<<128, 256>>>(emb);
    vq_main_kernel<<<GRID, 256, SMEM_BYTES>>>(z, emb, out);
}

// round 15
// speedup vs baseline: 1.8849x; 1.1496x over previous
#include <cuda_runtime.h>
#include <cstdint>

#define NUM_E   1024
#define DIM     128
#define HW      4096
#define NTILES  512           // 65536 rows / 128 per tile
#define GRID    304           // 2 per SM (152 SMs on GB300)
#define LASTV   (NTILES + GRID - 1)   // final atomicAdd return value per replay

// Output layout (flattened tuple, float32)
#define OFF_LOSS   8388608
#define OFF_IDX    8388609
#define OFF_COMMIT 8454145
#define OFF_CODE   8454146

#define DMARGIN 6e-4f         // margin in dot domain

__device__ float    d_enorm[NUM_E];
__device__ float    d_blockS[NTILES];
// bf16 codebook in m16n8k16 B-fragment order, as 32-bit (bf16x2) words:
// [s=j*8+kg 0..63][nb 0..7][lane 0..31][slot 0..3]
__device__ __align__(16) uint32_t d_bfrag16[65536];
__device__ unsigned d_tile = 0;

// SMEM (byte offsets), ~101KB -> 2 CTAs/SM
#define SM_A    0          // A bf16 frag layout, 32KB (mainloop only)
#define SM_ZPL  32768      // z tile f32 [d][n], 64KB
#define SM_CAND 0          // cand u32[128][24], 12KB — aliases A post-mainloop
#define SM_RB   16384      // refine best u64[2][128], 2KB — aliases A
// zqst f32[64][128] (32KB) aliases the whole A region during the epilogue
#define SM_E2   98304      // 1024 f32
#define SM_Z2   102400     // 128 f32
#define SM_IDX  102912     // 128 i32
#define SM_WSUM 103424     // 8 f32
#define SM_TILE 103456     // 1 i32
#define SMEM_BYTES 103488

static __device__ __forceinline__ uint32_t pack_bf16x2(float lo, float hi) {
    uint32_t r;
    asm("cvt.rn.bf16x2.f32 %0, %1, %2;" : "=r"(r) : "f"(hi), "f"(lo));
    return r;
}
static __device__ __forceinline__ void mma16(float c[4], const uint32_t a[4],
                                             uint32_t b0, uint32_t b1) {
    asm("mma.sync.aligned.m16n8k16.row.col.f32.bf16.bf16.f32 "
        "{%0,%1,%2,%3}, {%4,%5,%6,%7}, {%8,%9}, {%0,%1,%2,%3};"
        : "+f"(c[0]), "+f"(c[1]), "+f"(c[2]), "+f"(c[3])
        : "r"(a[0]), "r"(a[1]), "r"(a[2]), "r"(a[3]), "r"(b0), "r"(b1));
}

// ---------------------------------------------------------------------------
// Prep: ||e||^2 + bf16 codebook in m16n8k16 B-fragment order.
// ---------------------------------------------------------------------------
__global__ void prep_kernel(const float* __restrict__ emb) {
    int k    = blockIdx.x * 8 + (threadIdx.x >> 5);   // code id
    int lane = threadIdx.x & 31;
    const float4* row = (const float4*)(emb + (size_t)k * DIM);
    float4 v = row[lane];
    float s = __fadd_rn(__fadd_rn(__fmul_rn(v.x, v.x), __fmul_rn(v.y, v.y)),
                        __fadd_rn(__fmul_rn(v.z, v.z), __fmul_rn(v.w, v.w)));
    #pragma unroll
    for (int o = 16; o; o >>= 1) s = __fadd_rn(s, __shfl_xor_sync(0xffffffffu, s, o));
    if (lane == 0) d_enorm[k] = s;

    int j = k >> 7, loc = k & 127;
    int nb = loc >> 4, nn = loc & 15;
    int sub = nn >> 3, g = nn & 7;
    float vv[4] = {v.x, v.y, v.z, v.w};
    #pragma unroll
    for (int w = 0; w < 2; w++) {
        int d    = lane * 4 + w * 2;
        int kg   = d >> 4;
        int half = (d >> 3) & 1;
        int tig  = (d & 7) >> 1;
        int lane_f = g * 4 + tig;
        int slot = sub * 2 + half;
        uint32_t word = pack_bf16x2(vv[w * 2], vv[w * 2 + 1]);
        d_bfrag16[((((j * 8 + kg) * 8 + nb) * 32 + lane_f) * 4) + slot] = word;
    }
}

// ---------------------------------------------------------------------------
// Main: persistent, GRID x 256, 2 CTAs/SM, dynamic tile stealing.
// bf16 m16n8k16; B via direct __ldg ring; z tile in SMEM; split prologue;
// 2-way refine; staged coalesced epilogue.
// ---------------------------------------------------------------------------
__global__ __launch_bounds__(256, 2)
void vq_main_kernel(const float* __restrict__ z,
                    const float* __restrict__ emb,
                    float* __restrict__ out) {
    extern __shared__ char smem[];
    float* zpl   = (float*)(smem + SM_ZPL);
    float* e2sm  = (float*)(smem + SM_E2);
    float* z2sm  = (float*)(smem + SM_Z2);
    int*   idxsm = (int*)(smem + SM_IDX);
    float* wsum  = (float*)(smem + SM_WSUM);
    int*   stile = (int*)(smem + SM_TILE);
    uint32_t* cand = (uint32_t*)(smem + SM_CAND);
    unsigned long long* rbest = (unsigned long long*)(smem + SM_RB);
    float* zqst  = (float*)(smem + SM_A);      // epilogue staging (aliases A)

    const int t    = threadIdx.x;
    const int wid  = t >> 5;
    const int lane = t & 31;
    const int warp_m = wid >> 1;              // 0..3
    const int warp_n = wid & 1;               // 0..1
    const char* bgb = (const char*)d_bfrag16;

    // e2 table (persists across tiles)
    #pragma unroll
    for (int i = 0; i < 4; i++) e2sm[i * 256 + t] = d_enorm[i * 256 + t];

    // persistent B ring: preload s=0 into buffer 0
    uint4 bfr[2][4];
    {
        const char* pb = bgb + ((warp_n << 2) << 9) + (lane << 4);
        #pragma unroll
        for (int i = 0; i < 4; i++)
            bfr[0][i] = __ldg((const uint4*)(pb + (i << 9)));
    }

    int vtile;
    while (true) {
        __syncthreads();                       // smem reuse fence
        if (t == 0) *stile = (int)atomicAdd(&d_tile, 1u);
        __syncthreads();
        vtile = *stile;
        if (vtile >= NTILES) break;
        const int tile = vtile;
        const int n0  = tile * 128;
        const int b   = n0 >> 12;
        const int hw0 = n0 & 4095;
        const float* zbase = z + (size_t)b * (DIM * HW) + hw0;

        // ---- prologue A: fill zpl (coalesced float4, all 256 threads) ----
        #pragma unroll
        for (int i = 0; i < 16; i++) {
            int id = t + 256 * i;              // 4096 float4 = 128d x 128n
            int dl = id >> 5, hw4 = (id & 31) * 4;
            float4 v = *(const float4*)(zbase + (size_t)dl * HW + hw4);
            *(float4*)(&zpl[dl * 128 + hw4]) = v;
        }
        __syncthreads();

        // ---- prologue B (split): t<128 sequential z2; t>=128 A frags ----
        if (t < 128) {
            float z2 = 0.f;
            #pragma unroll 8
            for (int dp = 0; dp < 64; dp++) {
                int d = dp * 2;
                float v0 = zpl[d * 128 + t];
                float v1 = zpl[(d + 1) * 128 + t];
                z2 = __fadd_rn(__fadd_rn(z2, __fmul_rn(v0, v0)), __fmul_rn(v1, v1));
            }
            z2sm[t] = z2;
        } else {
            const int row = t - 128;
            const int mt = row >> 4, mm = row & 15;
            const int hm = mm >> 3, g = mm & 7;
            #pragma unroll 4
            for (int dp = 0; dp < 64; dp++) {
                int d = dp * 2;
                float v0 = zpl[d * 128 + row];
                float v1 = zpl[(d + 1) * 128 + row];
                int kg = d >> 4, half = (d >> 3) & 1, tig = (d & 7) >> 1;
                int reg = hm + 2 * half;
                int lane_f = g * 4 + tig;
                *(uint32_t*)(smem + SM_A
                    + ((((kg * 8 + mt) * 32 + lane_f) * 4 + reg) << 2))
                    = pack_bf16x2(v0, v1);
            }
        }
        __syncthreads();

        // top-3 max keys per pool (pool = (mf,h) row-slot)
        uint32_t kb0[4], kb1[4], kb2[4];
        #pragma unroll
        for (int i = 0; i < 4; i++) { kb0[i] = 0; kb1[i] = 0; kb2[i] = 0; }

        // ---- mainloop: barrier-free; B via direct LDG ring ----
        #pragma unroll 1
        for (int j = 0; j < 8; j++) {
            float acc[2][8][4];
            #pragma unroll
            for (int mf = 0; mf < 2; mf++)
                #pragma unroll
                for (int nf = 0; nf < 8; nf++)
                    #pragma unroll
                    for (int q = 0; q < 4; q++) acc[mf][nf][q] = 0.f;

            #pragma unroll
            for (int kg = 0; kg < 8; kg++) {
                {   // prefetch next s (wraps; B tile-invariant so wrap valid)
                    int sn = (j * 8 + kg + 1) & 63;
                    const char* pb = bgb + (((sn << 3) + (warp_n << 2)) << 9)
                                   + (lane << 4);
                    #pragma unroll
                    for (int i = 0; i < 4; i++)
                        bfr[(kg + 1) & 1][i] = __ldg((const uint4*)(pb + (i << 9)));
                }
                uint4 af[2];
                #pragma unroll
                for (int mf = 0; mf < 2; mf++)
                    af[mf] = *(const uint4*)(smem + SM_A + kg * 4096
                           + (warp_m * 2 + mf) * 512 + lane * 16);
                const uint4* bc = bfr[kg & 1];
                #pragma unroll
                for (int mf = 0; mf < 2; mf++) {
                    const uint32_t* av = (const uint32_t*)&af[mf];
                    #pragma unroll
                    for (int i = 0; i < 4; i++) {
                        mma16(acc[mf][i * 2 + 0], av, bc[i].x, bc[i].y);
                        mma16(acc[mf][i * 2 + 1], av, bc[i].z, bc[i].w);
                    }
                }
            }

            // shortlist scoring: key = (bits(max(dot,0)) & ~127) | local7
            #pragma unroll
            for (int mf = 0; mf < 2; mf++)
                #pragma unroll
                for (int nf = 0; nf < 8; nf++)
                    #pragma unroll
                    for (int h = 0; h < 2; h++)
                        #pragma unroll
                        for (int q = 0; q < 2; q++) {
                            float dc = fmaxf(acc[mf][nf][h * 2 + q], 0.0f);
                            uint32_t key = (__float_as_uint(dc) & 0xFFFFFF80u)
                                         | (uint32_t)((j << 4) | (nf << 1) | q);
                            int sl = mf * 2 + h;
                            uint32_t m01 = umin(key, kb0[sl]);
                            kb0[sl] = umax(key, kb0[sl]);
                            uint32_t m12 = umin(m01, kb1[sl]);
                            kb1[sl] = umax(m01, kb1[sl]);
                            kb2[sl] = umax(m12, kb2[sl]);
                        }
        }

        // ---- dump candidates: cand u32[128][24] (aliases A frags) ----
        __syncthreads();
        {
            int ci = warp_n * 4 + (lane & 3);          // 0..7
            #pragma unroll
            for (int mf = 0; mf < 2; mf++)
                #pragma unroll
                for (int h = 0; h < 2; h++) {
                    int m = warp_m * 32 + mf * 16 + h * 8 + (lane >> 2);
                    int sl = mf * 2 + h;
                    cand[m * 24 + ci * 3 + 0] = kb0[sl];
                    cand[m * 24 + ci * 3 + 1] = kb1[sl];
                    cand[m * 24 + ci * 3 + 2] = kb2[sl];
                }
        }
        __syncthreads();

        // ---- refine: 2 threads per row, interleaved candidate split ----
        {
            const int row  = t & 127;
            const int half = t >> 7;

            uint32_t maxk = 0;
            #pragma unroll
            for (int ci = 0; ci < 24; ci++) {
                uint32_t u = cand[row * 24 + ci];
                if (u > maxk) maxk = u;
            }
            float dmax = __uint_as_float(maxk & 0xFFFFFF80u);
            float thrf = dmax - DMARGIN;
            uint32_t kthr = (thrf > 0.f) ? (__float_as_uint(thrf) & 0xFFFFFF80u) : 0u;

            int cl[8]; int nc = 0;
            #pragma unroll
            for (int ci = 0; ci < 12; ci++) {
                int cig = ci * 2 + half;
                uint32_t u = cand[row * 24 + cig];
                if (u >= kthr && nc < 8) {
                    int loc = u & 127, pos = cig / 3;
                    cl[nc++] = ((loc >> 4) << 7) + ((pos >> 2) << 6)
                             + (((loc >> 1) & 7) << 3) + ((pos & 3) << 1) + (loc & 1);
                }
            }

            float a[8][4];
            #pragma unroll
            for (int i = 0; i < 8; i++)
                #pragma unroll
                for (int p = 0; p < 4; p++) a[i][p] = 0.f;
            #pragma unroll 4
            for (int q = 0; q < 32; q++) {
                int d0 = q * 4;
                float zv0 = zpl[(d0 + 0) * 128 + row];
                float zv1 = zpl[(d0 + 1) * 128 + row];
                float zv2 = zpl[(d0 + 2) * 128 + row];
                float zv3 = zpl[(d0 + 3) * 128 + row];
                #pragma unroll
                for (int i = 0; i < 8; i++) {
                    if (i < nc) {
                        float4 e4 = ((const float4*)(emb + (size_t)cl[i] * DIM))[q];
                        a[i][0] = fmaf(zv0, e4.x, a[i][0]);
                        a[i][1] = fmaf(zv1, e4.y, a[i][1]);
                        a[i][2] = fmaf(zv2, e4.z, a[i][2]);
                        a[i][3] = fmaf(zv3, e4.w, a[i][3]);
                    }
                }
            }
            float z2 = z2sm[row];
            unsigned long long bestu = ~0ull;
            for (int i = 0; i < nc; i++) {
                float dot = __fadd_rn(__fadd_rn(a[i][0], a[i][1]),
                                      __fadd_rn(a[i][2], a[i][3]));
                float s = __fadd_rn(__fadd_rn(z2, e2sm[cl[i]]),
                                    __fmul_rn(-2.0f, dot));
                unsigned long long u =
                    ((unsigned long long)__float_as_uint(s) << 32) | (unsigned)cl[i];
                if (u < bestu) bestu = u;
            }
            rbest[half * 128 + row] = bestu;
        }
        __syncthreads();
        if (t < 128) {
            unsigned long long u0 = rbest[t];
            unsigned long long u1 = rbest[128 + t];
            unsigned long long bu = (u0 < u1) ? u0 : u1;
            int idx = (int)(bu & 0xffffffffu);
            idxsm[t] = idx;
            out[OFF_IDX + n0 + t] = (float)idx;
        }

        // ---- epilogue: staged coalesced z_q, 2 halves of 64 rows ----
        float sloc = 0.f;
        #pragma unroll 1
        for (int half = 0; half < 2; half++) {
            __syncthreads();               // zqst region free (cand/rbest done)
            #pragma unroll
            for (int rr = 0; rr < 8; rr++) {
                int n  = half * 64 + wid * 8 + rr;
                int nb = n & 63;
                float4 ev = ((const float4*)(emb + (size_t)idxsm[n] * DIM))[lane];
                *(float4*)(&zqst[nb * 128 + ((lane ^ (nb & 7)) << 2)]) = ev;
            }
            __syncthreads();
            #pragma unroll 4
            for (int r = 0; r < 32; r++) {
                int linear = t + (r << 8);     // 0..8191
                int n64 = linear & 63;
                int d   = linear >> 6;
                int n   = half * 64 + n64;
                float v  = zqst[n64 * 128 + ((((d >> 2) ^ (n64 & 7)) << 2) | (d & 3))];
                float zv = zpl[d * 128 + n];
                float diff = v - zv;
                sloc = fmaf(diff, diff, sloc);
                out[(size_t)b * (DIM * HW) + (size_t)d * HW + hw0 + n] = v;
            }
        }
        #pragma unroll
        for (int o = 16; o; o >>= 1) sloc += __shfl_xor_sync(0xffffffffu, sloc, o);
        if (lane == 0) wsum[wid] = sloc;
        __syncthreads();
        if (t == 0) {
            float s = 0.f;
            #pragma unroll
            for (int i = 0; i < 8; i++) s += wsum[i];
            d_blockS[tile] = s;
            __threadfence();        // blockS visible before our next atomicAdd
        }
    }

    // ---- overshoot: the CTA whose grab returned LASTV finalizes + resets ----
    if (vtile == LASTV) {
        float* scratch = (float*)(smem + SM_CAND);
        scratch[t] = d_blockS[t] + d_blockS[t + 256];
        __syncthreads();
        for (int s = 128; s > 0; s >>= 1) {
            if (t < s) scratch[t] += scratch[t + s];
            __syncthreads();
        }
        if (t == 0) {
            float S = scratch[0];
            out[OFF_LOSS]   = 1.25f * S;
            out[OFF_COMMIT] = 0.25f * S;
            out[OFF_CODE]   = S;
            d_tile = 0;                         // last atomic user: safe reset
        }
    }
}

// ---------------------------------------------------------------------------
extern "C" void kernel_launch(void* const* d_in, const int* in_sizes, int n_in,
                              void* d_out, int out_size) {
    const float* z   = (const float*)d_in[0];   // (16, 128, 64, 64)
    const float* emb = (const float*)d_in[1];   // (1024, 128)
    float* out = (float*)d_out;

    cudaFuncSetAttribute(vq_main_kernel,
                         cudaFuncAttributeMaxDynamicSharedMemorySize, SMEM_BYTES);

    prep_kernel<<<128, 256>>>(emb);
    vq_main_kernel<<<GRID, 256, SMEM_BYTES>>>(z, emb, out);
}

// round 16
// speedup vs baseline: 2.0970x; 1.1125x over previous
#include <cuda_runtime.h>
#include <cstdint>

#define NUM_E   1024
#define DIM     128
#define HW      4096
#define NTILES  512           // 65536 rows / 128 per tile
#define GRID    304           // 2 per SM (152 SMs on GB300)
#define LASTV   (NTILES + GRID - 1)   // final atomicAdd return value per replay

// Output layout (flattened tuple, float32)
#define OFF_LOSS   8388608
#define OFF_IDX    8388609
#define OFF_COMMIT 8454145
#define OFF_CODE   8454146

#define DMARGIN 6e-4f         // margin in dot domain

__device__ float    d_enorm[NUM_E];
__device__ float    d_blockS[NTILES];
// bf16 codebook in m16n8k16 B-fragment order, as 32-bit (bf16x2) words:
// [s=j*8+kg 0..63][nb 0..7][lane 0..31][slot 0..3]
__device__ __align__(16) uint32_t d_bfrag16[65536];
__device__ unsigned d_tile = 0;

// SMEM (byte offsets), ~104KB -> 2 CTAs/SM
#define SM_A     0         // A bf16 frag layout, 32KB (mainloop only)
#define SM_CAND  0         // cand u32[128][24], 12KB — aliases A post-mainloop
#define SM_RB    12288     // rbest u64[128], 1KB — aliases A
#define SM_CLIST 13312     // clist u32[1024], 4KB — aliases A
#define SM_CNT   17408     // u32 — aliases A
// zqst f32[64][128] (32KB) aliases the whole A region during the epilogue
#define SM_ZROW  32768     // z tile f32 [n][129], 66048B
#define SM_E2    98816     // 1024 f32
#define SM_Z2    102912    // 128 f32
#define SM_IDX   103424    // 128 i32
#define SM_WSUM  103936    // 8 f32
#define SM_TILE  103968    // 1 i32
#define SMEM_BYTES 103984

static __device__ __forceinline__ uint32_t pack_bf16x2(float lo, float hi) {
    uint32_t r;
    asm("cvt.rn.bf16x2.f32 %0, %1, %2;" : "=r"(r) : "f"(hi), "f"(lo));
    return r;
}
static __device__ __forceinline__ void mma16(float c[4], const uint32_t a[4],
                                             uint32_t b0, uint32_t b1) {
    asm("mma.sync.aligned.m16n8k16.row.col.f32.bf16.bf16.f32 "
        "{%0,%1,%2,%3}, {%4,%5,%6,%7}, {%8,%9}, {%0,%1,%2,%3};"
        : "+f"(c[0]), "+f"(c[1]), "+f"(c[2]), "+f"(c[3])
        : "r"(a[0]), "r"(a[1]), "r"(a[2]), "r"(a[3]), "r"(b0), "r"(b1));
}

// ---------------------------------------------------------------------------
// Prep: ||e||^2 + bf16 codebook in m16n8k16 B-fragment order.
// ---------------------------------------------------------------------------
__global__ void prep_kernel(const float* __restrict__ emb) {
    int k    = blockIdx.x * 8 + (threadIdx.x >> 5);   // code id
    int lane = threadIdx.x & 31;
    const float4* row = (const float4*)(emb + (size_t)k * DIM);
    float4 v = row[lane];
    float s = __fadd_rn(__fadd_rn(__fmul_rn(v.x, v.x), __fmul_rn(v.y, v.y)),
                        __fadd_rn(__fmul_rn(v.z, v.z), __fmul_rn(v.w, v.w)));
    #pragma unroll
    for (int o = 16; o; o >>= 1) s = __fadd_rn(s, __shfl_xor_sync(0xffffffffu, s, o));
    if (lane == 0) d_enorm[k] = s;

    int j = k >> 7, loc = k & 127;
    int nb = loc >> 4, nn = loc & 15;
    int sub = nn >> 3, g = nn & 7;
    float vv[4] = {v.x, v.y, v.z, v.w};
    #pragma unroll
    for (int w = 0; w < 2; w++) {
        int d    = lane * 4 + w * 2;
        int kg   = d >> 4;
        int half = (d >> 3) & 1;
        int tig  = (d & 7) >> 1;
        int lane_f = g * 4 + tig;
        int slot = sub * 2 + half;
        uint32_t word = pack_bf16x2(vv[w * 2], vv[w * 2 + 1]);
        d_bfrag16[((((j * 8 + kg) * 8 + nb) * 32 + lane_f) * 4) + slot] = word;
    }
}

// ---------------------------------------------------------------------------
// Main: persistent, GRID x 256, 2 CTAs/SM, dynamic tile stealing.
// bf16 m16n8k16; B via direct __ldg ring; z row-major in SMEM (pad 129);
// warp-cooperative exact refine on compact candidate list; staged epilogue.
// ---------------------------------------------------------------------------
__global__ __launch_bounds__(256, 2)
void vq_main_kernel(const float* __restrict__ z,
                    const float* __restrict__ emb,
                    float* __restrict__ out) {
    extern __shared__ char smem[];
    float* zrow  = (float*)(smem + SM_ZROW);   // zrow[n*129 + d]
    float* e2sm  = (float*)(smem + SM_E2);
    float* z2sm  = (float*)(smem + SM_Z2);
    int*   idxsm = (int*)(smem + SM_IDX);
    float* wsum  = (float*)(smem + SM_WSUM);
    int*   stile = (int*)(smem + SM_TILE);
    uint32_t* cand  = (uint32_t*)(smem + SM_CAND);
    unsigned long long* rbest = (unsigned long long*)(smem + SM_RB);
    uint32_t* clist = (uint32_t*)(smem + SM_CLIST);
    int*   pcnt  = (int*)(smem + SM_CNT);
    float* zqst  = (float*)(smem + SM_A);      // epilogue staging (aliases A)

    const int t    = threadIdx.x;
    const int wid  = t >> 5;
    const int lane = t & 31;
    const int warp_m = wid >> 1;              // 0..3
    const int warp_n = wid & 1;               // 0..1
    const char* bgb = (const char*)d_bfrag16;

    // e2 table (persists across tiles)
    #pragma unroll
    for (int i = 0; i < 4; i++) e2sm[i * 256 + t] = d_enorm[i * 256 + t];

    // persistent B ring: preload s=0 into buffer 0
    uint4 bfr[2][4];
    {
        const char* pb = bgb + ((warp_n << 2) << 9) + (lane << 4);
        #pragma unroll
        for (int i = 0; i < 4; i++)
            bfr[0][i] = __ldg((const uint4*)(pb + (i << 9)));
    }

    int vtile;
    while (true) {
        __syncthreads();                       // smem reuse fence
        if (t == 0) *stile = (int)atomicAdd(&d_tile, 1u);
        __syncthreads();
        vtile = *stile;
        if (vtile >= NTILES) break;
        const int tile = vtile;
        const int n0  = tile * 128;
        const int b   = n0 >> 12;
        const int hw0 = n0 & 4095;
        const float* zbase = z + (size_t)b * (DIM * HW) + hw0;

        // ---- prologue A: fill zrow[n][129] (coalesced gmem, scalar STS) ----
        #pragma unroll
        for (int i = 0; i < 16; i++) {
            int id = t + 256 * i;              // 4096 float4 = 128d x 128n
            int dl = id >> 5, n4 = (id & 31) * 4;
            float4 v = *(const float4*)(zbase + (size_t)dl * HW + n4);
            zrow[(n4 + 0) * 129 + dl] = v.x;
            zrow[(n4 + 1) * 129 + dl] = v.y;
            zrow[(n4 + 2) * 129 + dl] = v.z;
            zrow[(n4 + 3) * 129 + dl] = v.w;
        }
        __syncthreads();

        // ---- prologue B (split): t<128 sequential z2; t>=128 A frags ----
        if (t < 128) {
            const float* zr = zrow + t * 129;
            float z2 = 0.f;
            #pragma unroll 8
            for (int d = 0; d < 128; d++) {
                float v = zr[d];
                z2 = __fadd_rn(z2, __fmul_rn(v, v));
            }
            z2sm[t] = z2;
        } else {
            const int row = t - 128;
            const float* zr = zrow + row * 129;
            const int mt = row >> 4, mm = row & 15;
            const int hm = mm >> 3, g = mm & 7;
            #pragma unroll 4
            for (int dp = 0; dp < 64; dp++) {
                int d = dp * 2;
                float v0 = zr[d];
                float v1 = zr[d + 1];
                int kg = d >> 4, half = (d >> 3) & 1, tig = (d & 7) >> 1;
                int reg = hm + 2 * half;
                int lane_f = g * 4 + tig;
                *(uint32_t*)(smem + SM_A
                    + ((((kg * 8 + mt) * 32 + lane_f) * 4 + reg) << 2))
                    = pack_bf16x2(v0, v1);
            }
        }
        __syncthreads();

        // top-3 max keys per pool (pool = (mf,h) row-slot)
        uint32_t kb0[4], kb1[4], kb2[4];
        #pragma unroll
        for (int i = 0; i < 4; i++) { kb0[i] = 0; kb1[i] = 0; kb2[i] = 0; }

        // ---- mainloop: barrier-free; B via direct LDG ring ----
        #pragma unroll 1
        for (int j = 0; j < 8; j++) {
            float acc[2][8][4];
            #pragma unroll
            for (int mf = 0; mf < 2; mf++)
                #pragma unroll
                for (int nf = 0; nf < 8; nf++)
                    #pragma unroll
                    for (int q = 0; q < 4; q++) acc[mf][nf][q] = 0.f;

            #pragma unroll
            for (int kg = 0; kg < 8; kg++) {
                {   // prefetch next s (wraps; B tile-invariant so wrap valid)
                    int sn = (j * 8 + kg + 1) & 63;
                    const char* pb = bgb + (((sn << 3) + (warp_n << 2)) << 9)
                                   + (lane << 4);
                    #pragma unroll
                    for (int i = 0; i < 4; i++)
                        bfr[(kg + 1) & 1][i] = __ldg((const uint4*)(pb + (i << 9)));
                }
                uint4 af[2];
                #pragma unroll
                for (int mf = 0; mf < 2; mf++)
                    af[mf] = *(const uint4*)(smem + SM_A + kg * 4096
                           + (warp_m * 2 + mf) * 512 + lane * 16);
                const uint4* bc = bfr[kg & 1];
                #pragma unroll
                for (int mf = 0; mf < 2; mf++) {
                    const uint32_t* av = (const uint32_t*)&af[mf];
                    #pragma unroll
                    for (int i = 0; i < 4; i++) {
                        mma16(acc[mf][i * 2 + 0], av, bc[i].x, bc[i].y);
                        mma16(acc[mf][i * 2 + 1], av, bc[i].z, bc[i].w);
                    }
                }
            }

            // shortlist scoring: key = (bits(max(dot,0)) & ~127) | local7
            #pragma unroll
            for (int mf = 0; mf < 2; mf++)
                #pragma unroll
                for (int nf = 0; nf < 8; nf++)
                    #pragma unroll
                    for (int h = 0; h < 2; h++)
                        #pragma unroll
                        for (int q = 0; q < 2; q++) {
                            float dc = fmaxf(acc[mf][nf][h * 2 + q], 0.0f);
                            uint32_t key = (__float_as_uint(dc) & 0xFFFFFF80u)
                                         | (uint32_t)((j << 4) | (nf << 1) | q);
                            int sl = mf * 2 + h;
                            uint32_t m01 = umin(key, kb0[sl]);
                            kb0[sl] = umax(key, kb0[sl]);
                            uint32_t m12 = umin(m01, kb1[sl]);
                            kb1[sl] = umax(m01, kb1[sl]);
                            kb2[sl] = umax(m12, kb2[sl]);
                        }
        }

        // ---- dump candidates: cand u32[128][24] (aliases A frags) ----
        __syncthreads();
        if (t == 0) *pcnt = 0;
        {
            int ci = warp_n * 4 + (lane & 3);          // 0..7
            #pragma unroll
            for (int mf = 0; mf < 2; mf++)
                #pragma unroll
                for (int h = 0; h < 2; h++) {
                    int m = warp_m * 32 + mf * 16 + h * 8 + (lane >> 2);
                    int sl = mf * 2 + h;
                    cand[m * 24 + ci * 3 + 0] = kb0[sl];
                    cand[m * 24 + ci * 3 + 1] = kb1[sl];
                    cand[m * 24 + ci * 3 + 2] = kb2[sl];
                }
        }
        __syncthreads();

        // ---- select: per row, margin filter -> compact clist ----
        if (t < 128) {
            rbest[t] = ~0ull;
            uint32_t maxk = 0; int maxci = 0;
            #pragma unroll
            for (int ci = 0; ci < 24; ci++) {
                uint32_t u = cand[t * 24 + ci];
                if (u > maxk) { maxk = u; maxci = ci; }
            }
            float dmax = __uint_as_float(maxk & 0xFFFFFF80u);
            float thrf = dmax - DMARGIN;
            uint32_t kthr = (thrf > 0.f) ? (__float_as_uint(thrf) & 0xFFFFFF80u) : 0u;

            // decode: code = j*128 + wn*64 + nf*8 + lq*2 + q (wn=pos>>2, lq=pos&3)
            int nc = 0;
            {
                int loc = maxk & 127, pos = maxci / 3;
                int code = ((loc >> 4) << 7) + ((pos >> 2) << 6)
                         + (((loc >> 1) & 7) << 3) + ((pos & 3) << 1) + (loc & 1);
                int p = atomicAdd(pcnt, 1);
                clist[p] = (uint32_t)((t << 10) | code);
                nc = 1;
            }
            #pragma unroll
            for (int ci = 0; ci < 24; ci++) {
                uint32_t u = cand[t * 24 + ci];
                if (ci != maxci && u >= kthr && nc < 8) {
                    int loc = u & 127, pos = ci / 3;
                    int code = ((loc >> 4) << 7) + ((pos >> 2) << 6)
                             + (((loc >> 1) & 7) << 3) + ((pos & 3) << 1) + (loc & 1);
                    int p = atomicAdd(pcnt, 1);
                    clist[p] = (uint32_t)((t << 10) | code);
                    nc++;
                }
            }
        }
        __syncthreads();

        // ---- warp-cooperative EXACT refine over the candidate list ----
        {
            const int ncand = *pcnt;
            #pragma unroll 2
            for (int e = wid; e < ncand; e += 8) {
                uint32_t u = clist[e];
                int row = u >> 10;
                int k   = u & 1023;
                const float* zr = zrow + row * 129;
                const float* er = emb + (size_t)k * DIM;
                float p = 0.f;
                #pragma unroll
                for (int jj = 0; jj < 4; jj++) {
                    int d = lane + 32 * jj;
                    p = fmaf(zr[d], __ldg(er + d), p);
                }
                #pragma unroll
                for (int o = 16; o; o >>= 1)
                    p = __fadd_rn(p, __shfl_xor_sync(0xffffffffu, p, o));
                if (lane == 0) {
                    float s = __fadd_rn(__fadd_rn(z2sm[row], e2sm[k]),
                                        __fmul_rn(-2.0f, p));
                    unsigned long long key =
                        ((unsigned long long)__float_as_uint(s) << 32) | (unsigned)k;
                    atomicMin(&rbest[row], key);
                }
            }
        }
        __syncthreads();
        if (t < 128) {
            int idx = (int)(rbest[t] & 1023u);
            idxsm[t] = idx;
            out[OFF_IDX + n0 + t] = (float)idx;
        }

        // ---- epilogue: staged coalesced z_q, 2 halves of 64 rows ----
        float sloc = 0.f;
        #pragma unroll 1
        for (int half = 0; half < 2; half++) {
            __syncthreads();               // zqst region free (cand/clist done)
            #pragma unroll
            for (int rr = 0; rr < 8; rr++) {
                int n  = half * 64 + wid * 8 + rr;
                int nb = n & 63;
                float4 ev = ((const float4*)(emb + (size_t)idxsm[n] * DIM))[lane];
                *(float4*)(&zqst[nb * 128 + ((lane ^ (nb & 7)) << 2)]) = ev;
            }
            __syncthreads();
            #pragma unroll 4
            for (int r = 0; r < 32; r++) {
                int linear = t + (r << 8);     // 0..8191
                int n64 = linear & 63;
                int d   = linear >> 6;
                int n   = half * 64 + n64;
                float v  = zqst[n64 * 128 + ((((d >> 2) ^ (n64 & 7)) << 2) | (d & 3))];
                float zv = zrow[n * 129 + d];
                float diff = v - zv;
                sloc = fmaf(diff, diff, sloc);
                out[(size_t)b * (DIM * HW) + (size_t)d * HW + hw0 + n] = v;
            }
        }
        #pragma unroll
        for (int o = 16; o; o >>= 1) sloc += __shfl_xor_sync(0xffffffffu, sloc, o);
        if (lane == 0) wsum[wid] = sloc;
        __syncthreads();
        if (t == 0) {
            float s = 0.f;
            #pragma unroll
            for (int i = 0; i < 8; i++) s += wsum[i];
            d_blockS[tile] = s;
            __threadfence();        // blockS visible before our next atomicAdd
        }
    }

    // ---- overshoot: the CTA whose grab returned LASTV finalizes + resets ----
    if (vtile == LASTV) {
        float* scratch = (float*)(smem + SM_CAND);
        scratch[t] = d_blockS[t] + d_blockS[t + 256];
        __syncthreads();
        for (int s = 128; s > 0; s >>= 1) {
            if (t < s) scratch[t] += scratch[t + s];
            __syncthreads();
        }
        if (t == 0) {
            float S = scratch[0];
            out[OFF_LOSS]   = 1.25f * S;
            out[OFF_COMMIT] = 0.25f * S;
            out[OFF_CODE]   = S;
            d_tile = 0;                         // last atomic user: safe reset
        }
    }
}

// ---------------------------------------------------------------------------
extern "C" void kernel_launch(void* const* d_in, const int* in_sizes, int n_in,
                              void* d_out, int out_size) {
    const float* z   = (const float*)d_in[0];   // (16, 128, 64, 64)
    const float* emb = (const float*)d_in[1];   // (1024, 128)
    float* out = (float*)d_out;

    cudaFuncSetAttribute(vq_main_kernel,
                         cudaFuncAttributeMaxDynamicSharedMemorySize, SMEM_BYTES);

    prep_kernel<<<128, 256>>>(emb);
    vq_main_kernel<<<GRID, 256, SMEM_BYTES>>>(z, emb, out);
}

// round 17
// speedup vs baseline: 2.1408x; 1.0209x over previous
#include <cuda_runtime.h>
#include <cstdint>

#define NUM_E   1024
#define DIM     128
#define HW      4096
#define NTILES  512           // 65536 rows / 128 per tile
#define GRID    304           // 2 per SM (152 SMs on GB300)
#define LASTV   (NTILES + GRID - 1)   // final atomicAdd return value per replay

// Output layout (flattened tuple, float32)
#define OFF_LOSS   8388608
#define OFF_IDX    8388609
#define OFF_COMMIT 8454145
#define OFF_CODE   8454146

#define DMARGIN 6e-4f         // margin in dot domain

__device__ float    d_enorm[NUM_E];
__device__ float    d_blockS[NTILES];
// bf16 codebook in m16n8k16 B-fragment order, as 32-bit (bf16x2) words:
// [s=j*8+kg 0..63][nb 0..7][lane 0..31][slot 0..3]
__device__ __align__(16) uint32_t d_bfrag16[65536];
__device__ unsigned d_tile = 0;

// SMEM (byte offsets), ~104KB -> 2 CTAs/SM
#define SM_A     0         // A bf16 frag layout, 32KB (mainloop only)
#define SM_CAND  0         // cand u32[128][24], 12KB — aliases A post-mainloop
#define SM_RB    12288     // rbest u64[128], 1KB — aliases A
#define SM_CLIST 13312     // clist u32[1024], 4KB — aliases A
#define SM_CNT   17408     // u32 — aliases A
// zqst f32[64][128] (32KB) aliases the whole A region during the epilogue
#define SM_ZROW  32768     // z tile f32 [n][129], 66048B
#define SM_E2    98816     // 1024 f32
#define SM_Z2    102912    // 128 f32
#define SM_IDX   103424    // 128 i32
#define SM_TILE  103936    // 1 i32
#define SMEM_BYTES 103952

static __device__ __forceinline__ uint32_t pack_bf16x2(float lo, float hi) {
    uint32_t r;
    asm("cvt.rn.bf16x2.f32 %0, %1, %2;" : "=r"(r) : "f"(hi), "f"(lo));
    return r;
}
static __device__ __forceinline__ void mma16(float c[4], const uint32_t a[4],
                                             uint32_t b0, uint32_t b1) {
    asm("mma.sync.aligned.m16n8k16.row.col.f32.bf16.bf16.f32 "
        "{%0,%1,%2,%3}, {%4,%5,%6,%7}, {%8,%9}, {%0,%1,%2,%3};"
        : "+f"(c[0]), "+f"(c[1]), "+f"(c[2]), "+f"(c[3])
        : "r"(a[0]), "r"(a[1]), "r"(a[2]), "r"(a[3]), "r"(b0), "r"(b1));
}

// ---------------------------------------------------------------------------
// Prep: ||e||^2 + bf16 codebook in m16n8k16 B-fragment order.
// ---------------------------------------------------------------------------
__global__ void prep_kernel(const float* __restrict__ emb) {
    int k    = blockIdx.x * 8 + (threadIdx.x >> 5);   // code id
    int lane = threadIdx.x & 31;
    const float4* row = (const float4*)(emb + (size_t)k * DIM);
    float4 v = row[lane];
    float s = __fadd_rn(__fadd_rn(__fmul_rn(v.x, v.x), __fmul_rn(v.y, v.y)),
                        __fadd_rn(__fmul_rn(v.z, v.z), __fmul_rn(v.w, v.w)));
    #pragma unroll
    for (int o = 16; o; o >>= 1) s = __fadd_rn(s, __shfl_xor_sync(0xffffffffu, s, o));
    if (lane == 0) d_enorm[k] = s;

    int j = k >> 7, loc = k & 127;
    int nb = loc >> 4, nn = loc & 15;
    int sub = nn >> 3, g = nn & 7;
    float vv[4] = {v.x, v.y, v.z, v.w};
    #pragma unroll
    for (int w = 0; w < 2; w++) {
        int d    = lane * 4 + w * 2;
        int kg   = d >> 4;
        int half = (d >> 3) & 1;
        int tig  = (d & 7) >> 1;
        int lane_f = g * 4 + tig;
        int slot = sub * 2 + half;
        uint32_t word = pack_bf16x2(vv[w * 2], vv[w * 2 + 1]);
        d_bfrag16[((((j * 8 + kg) * 8 + nb) * 32 + lane_f) * 4) + slot] = word;
    }
}

// ---------------------------------------------------------------------------
// Main: persistent, GRID x 256, 2 CTAs/SM, dynamic tile stealing.
// bf16 m16n8k16; B via direct __ldg ring; z row-major in SMEM (pad 129);
// warp-cooperative exact refine; LOSS TAKEN FROM REFINE SCORES (free);
// staged coalesced epilogue (write-only).
// ---------------------------------------------------------------------------
__global__ __launch_bounds__(256, 2)
void vq_main_kernel(const float* __restrict__ z,
                    const float* __restrict__ emb,
                    float* __restrict__ out) {
    extern __shared__ char smem[];
    float* zrow  = (float*)(smem + SM_ZROW);   // zrow[n*129 + d]
    float* e2sm  = (float*)(smem + SM_E2);
    float* z2sm  = (float*)(smem + SM_Z2);
    int*   idxsm = (int*)(smem + SM_IDX);
    int*   stile = (int*)(smem + SM_TILE);
    uint32_t* cand  = (uint32_t*)(smem + SM_CAND);
    unsigned long long* rbest = (unsigned long long*)(smem + SM_RB);
    uint32_t* clist = (uint32_t*)(smem + SM_CLIST);
    int*   pcnt  = (int*)(smem + SM_CNT);
    float* zqst  = (float*)(smem + SM_A);      // epilogue staging (aliases A)

    const int t    = threadIdx.x;
    const int wid  = t >> 5;
    const int lane = t & 31;
    const int warp_m = wid >> 1;              // 0..3
    const int warp_n = wid & 1;               // 0..1
    const char* bgb = (const char*)d_bfrag16;

    // e2 table (persists across tiles)
    #pragma unroll
    for (int i = 0; i < 4; i++) e2sm[i * 256 + t] = d_enorm[i * 256 + t];

    // persistent B ring: preload s=0 into buffer 0
    uint4 bfr[2][4];
    {
        const char* pb = bgb + ((warp_n << 2) << 9) + (lane << 4);
        #pragma unroll
        for (int i = 0; i < 4; i++)
            bfr[0][i] = __ldg((const uint4*)(pb + (i << 9)));
    }

    int vtile;
    while (true) {
        __syncthreads();                       // smem reuse fence
        if (t == 0) *stile = (int)atomicAdd(&d_tile, 1u);
        __syncthreads();
        vtile = *stile;
        if (vtile >= NTILES) break;
        const int tile = vtile;
        const int n0  = tile * 128;
        const int b   = n0 >> 12;
        const int hw0 = n0 & 4095;
        const float* zbase = z + (size_t)b * (DIM * HW) + hw0;

        // ---- prologue A: fill zrow[n][129] (coalesced gmem, scalar STS) ----
        #pragma unroll
        for (int i = 0; i < 16; i++) {
            int id = t + 256 * i;              // 4096 float4 = 128d x 128n
            int dl = id >> 5, n4 = (id & 31) * 4;
            float4 v = *(const float4*)(zbase + (size_t)dl * HW + n4);
            zrow[(n4 + 0) * 129 + dl] = v.x;
            zrow[(n4 + 1) * 129 + dl] = v.y;
            zrow[(n4 + 2) * 129 + dl] = v.z;
            zrow[(n4 + 3) * 129 + dl] = v.w;
        }
        __syncthreads();

        // ---- prologue B (split): t<128 sequential z2; t>=128 A frags ----
        if (t < 128) {
            const float* zr = zrow + t * 129;
            float z2 = 0.f;
            #pragma unroll 8
            for (int d = 0; d < 128; d++) {
                float v = zr[d];
                z2 = __fadd_rn(z2, __fmul_rn(v, v));
            }
            z2sm[t] = z2;
        } else {
            const int row = t - 128;
            const float* zr = zrow + row * 129;
            const int mt = row >> 4, mm = row & 15;
            const int hm = mm >> 3, g = mm & 7;
            #pragma unroll 4
            for (int dp = 0; dp < 64; dp++) {
                int d = dp * 2;
                float v0 = zr[d];
                float v1 = zr[d + 1];
                int kg = d >> 4, half = (d >> 3) & 1, tig = (d & 7) >> 1;
                int reg = hm + 2 * half;
                int lane_f = g * 4 + tig;
                *(uint32_t*)(smem + SM_A
                    + ((((kg * 8 + mt) * 32 + lane_f) * 4 + reg) << 2))
                    = pack_bf16x2(v0, v1);
            }
        }
        __syncthreads();

        // top-3 max keys per pool (pool = (mf,h) row-slot)
        uint32_t kb0[4], kb1[4], kb2[4];
        #pragma unroll
        for (int i = 0; i < 4; i++) { kb0[i] = 0; kb1[i] = 0; kb2[i] = 0; }

        // ---- mainloop: barrier-free; B via direct LDG ring ----
        #pragma unroll 1
        for (int j = 0; j < 8; j++) {
            float acc[2][8][4];
            #pragma unroll
            for (int mf = 0; mf < 2; mf++)
                #pragma unroll
                for (int nf = 0; nf < 8; nf++)
                    #pragma unroll
                    for (int q = 0; q < 4; q++) acc[mf][nf][q] = 0.f;

            #pragma unroll
            for (int kg = 0; kg < 8; kg++) {
                {   // prefetch next s (wraps; B tile-invariant so wrap valid)
                    int sn = (j * 8 + kg + 1) & 63;
                    const char* pb = bgb + (((sn << 3) + (warp_n << 2)) << 9)
                                   + (lane << 4);
                    #pragma unroll
                    for (int i = 0; i < 4; i++)
                        bfr[(kg + 1) & 1][i] = __ldg((const uint4*)(pb + (i << 9)));
                }
                uint4 af[2];
                #pragma unroll
                for (int mf = 0; mf < 2; mf++)
                    af[mf] = *(const uint4*)(smem + SM_A + kg * 4096
                           + (warp_m * 2 + mf) * 512 + lane * 16);
                const uint4* bc = bfr[kg & 1];
                #pragma unroll
                for (int mf = 0; mf < 2; mf++) {
                    const uint32_t* av = (const uint32_t*)&af[mf];
                    #pragma unroll
                    for (int i = 0; i < 4; i++) {
                        mma16(acc[mf][i * 2 + 0], av, bc[i].x, bc[i].y);
                        mma16(acc[mf][i * 2 + 1], av, bc[i].z, bc[i].w);
                    }
                }
            }

            // shortlist scoring: key = (bits(max(dot,0)) & ~127) | local7
            #pragma unroll
            for (int mf = 0; mf < 2; mf++)
                #pragma unroll
                for (int nf = 0; nf < 8; nf++)
                    #pragma unroll
                    for (int h = 0; h < 2; h++)
                        #pragma unroll
                        for (int q = 0; q < 2; q++) {
                            float dc = fmaxf(acc[mf][nf][h * 2 + q], 0.0f);
                            uint32_t key = (__float_as_uint(dc) & 0xFFFFFF80u)
                                         | (uint32_t)((j << 4) | (nf << 1) | q);
                            int sl = mf * 2 + h;
                            uint32_t m01 = umin(key, kb0[sl]);
                            kb0[sl] = umax(key, kb0[sl]);
                            uint32_t m12 = umin(m01, kb1[sl]);
                            kb1[sl] = umax(m01, kb1[sl]);
                            kb2[sl] = umax(m12, kb2[sl]);
                        }
        }

        // ---- dump candidates: cand u32[128][24] (aliases A frags) ----
        __syncthreads();
        if (t == 0) *pcnt = 0;
        {
            int ci = warp_n * 4 + (lane & 3);          // 0..7
            #pragma unroll
            for (int mf = 0; mf < 2; mf++)
                #pragma unroll
                for (int h = 0; h < 2; h++) {
                    int m = warp_m * 32 + mf * 16 + h * 8 + (lane >> 2);
                    int sl = mf * 2 + h;
                    cand[m * 24 + ci * 3 + 0] = kb0[sl];
                    cand[m * 24 + ci * 3 + 1] = kb1[sl];
                    cand[m * 24 + ci * 3 + 2] = kb2[sl];
                }
        }
        __syncthreads();

        // ---- select: per row, margin filter -> compact clist ----
        if (t < 128) {
            rbest[t] = ~0ull;
            uint32_t maxk = 0; int maxci = 0;
            #pragma unroll
            for (int ci = 0; ci < 24; ci++) {
                uint32_t u = cand[t * 24 + ci];
                if (u > maxk) { maxk = u; maxci = ci; }
            }
            float dmax = __uint_as_float(maxk & 0xFFFFFF80u);
            float thrf = dmax - DMARGIN;
            uint32_t kthr = (thrf > 0.f) ? (__float_as_uint(thrf) & 0xFFFFFF80u) : 0u;

            // decode: code = j*128 + wn*64 + nf*8 + lq*2 + q (wn=pos>>2, lq=pos&3)
            int nc = 0;
            {
                int loc = maxk & 127, pos = maxci / 3;
                int code = ((loc >> 4) << 7) + ((pos >> 2) << 6)
                         + (((loc >> 1) & 7) << 3) + ((pos & 3) << 1) + (loc & 1);
                int p = atomicAdd(pcnt, 1);
                clist[p] = (uint32_t)((t << 10) | code);
                nc = 1;
            }
            #pragma unroll
            for (int ci = 0; ci < 24; ci++) {
                uint32_t u = cand[t * 24 + ci];
                if (ci != maxci && u >= kthr && nc < 8) {
                    int loc = u & 127, pos = ci / 3;
                    int code = ((loc >> 4) << 7) + ((pos >> 2) << 6)
                             + (((loc >> 1) & 7) << 3) + ((pos & 3) << 1) + (loc & 1);
                    int p = atomicAdd(pcnt, 1);
                    clist[p] = (uint32_t)((t << 10) | code);
                    nc++;
                }
            }
        }
        __syncthreads();

        // ---- warp-cooperative EXACT refine over the candidate list ----
        {
            const int ncand = *pcnt;
            #pragma unroll 2
            for (int e = wid; e < ncand; e += 8) {
                uint32_t u = clist[e];
                int row = u >> 10;
                int k   = u & 1023;
                const float* zr = zrow + row * 129;
                const float* er = emb + (size_t)k * DIM;
                float p = 0.f;
                #pragma unroll
                for (int jj = 0; jj < 4; jj++) {
                    int d = lane + 32 * jj;
                    p = fmaf(zr[d], __ldg(er + d), p);
                }
                #pragma unroll
                for (int o = 16; o; o >>= 1)
                    p = __fadd_rn(p, __shfl_xor_sync(0xffffffffu, p, o));
                if (lane == 0) {
                    float s = __fadd_rn(__fadd_rn(z2sm[row], e2sm[k]),
                                        __fmul_rn(-2.0f, p));
                    unsigned long long key =
                        ((unsigned long long)__float_as_uint(s) << 32) | (unsigned)k;
                    atomicMin(&rbest[row], key);
                }
            }
        }
        __syncthreads();
        if (t < 128) {
            int idx = (int)(rbest[t] & 1023u);
            idxsm[t] = idx;
            out[OFF_IDX + n0 + t] = (float)idx;
        }
        // ---- per-tile loss from refine scores: S = sum of winning scores ----
        if (wid == 0) {
            float s = 0.f;
            #pragma unroll
            for (int i = 0; i < 4; i++)
                s = __fadd_rn(s, __uint_as_float(
                        (uint32_t)(rbest[lane + 32 * i] >> 32)));
            #pragma unroll
            for (int o = 16; o; o >>= 1)
                s = __fadd_rn(s, __shfl_xor_sync(0xffffffffu, s, o));
            if (lane == 0) {
                d_blockS[tile] = s;
                __threadfence();   // visible before this CTA's next atomicAdd
            }
        }

        // ---- epilogue: staged coalesced z_q write (no loss math) ----
        #pragma unroll 1
        for (int half = 0; half < 2; half++) {
            __syncthreads();               // zqst region free (cand/rbest done)
            #pragma unroll
            for (int rr = 0; rr < 8; rr++) {
                int n  = half * 64 + wid * 8 + rr;
                int nb = n & 63;
                float4 ev = ((const float4*)(emb + (size_t)idxsm[n] * DIM))[lane];
                *(float4*)(&zqst[nb * 128 + ((lane ^ (nb & 7)) << 2)]) = ev;
            }
            __syncthreads();
            #pragma unroll 4
            for (int r = 0; r < 32; r++) {
                int linear = t + (r << 8);     // 0..8191
                int n64 = linear & 63;
                int d   = linear >> 6;
                int n   = half * 64 + n64;
                float v = zqst[n64 * 128 + ((((d >> 2) ^ (n64 & 7)) << 2) | (d & 3))];
                out[(size_t)b * (DIM * HW) + (size_t)d * HW + hw0 + n] = v;
            }
        }
    }

    // ---- overshoot: the CTA whose grab returned LASTV finalizes + resets ----
    if (vtile == LASTV) {
        float* scratch = (float*)(smem + SM_CAND);
        scratch[t] = d_blockS[t] + d_blockS[t + 256];
        __syncthreads();
        for (int s = 128; s > 0; s >>= 1) {
            if (t < s) scratch[t] += scratch[t + s];
            __syncthreads();
        }
        if (t == 0) {
            float S = scratch[0];
            out[OFF_LOSS]   = 1.25f * S;
            out[OFF_COMMIT] = 0.25f * S;
            out[OFF_CODE]   = S;
            d_tile = 0;                         // last atomic user: safe reset
        }
    }
}

// ---------------------------------------------------------------------------
extern "C" void kernel_launch(void* const* d_in, const int* in_sizes, int n_in,
                              void* d_out, int out_size) {
    const float* z   = (const float*)d_in[0];   // (16, 128, 64, 64)
    const float* emb = (const float*)d_in[1];   // (1024, 128)
    float* out = (float*)d_out;

    cudaFuncSetAttribute(vq_main_kernel,
                         cudaFuncAttributeMaxDynamicSharedMemorySize, SMEM_BYTES);

    prep_kernel<<<128, 256>>>(emb);
    vq_main_kernel<<<GRID, 256, SMEM_BYTES>>>(z, emb, out);
}